// round 3
// baseline (speedup 1.0000x reference)
#include <cuda_runtime.h>
#include <math.h>
#include <stdint.h>

// ---------------- problem constants ----------------
constexpr int B_  = 2;
constexpr int C_  = 1024;
constexpr int H_  = 16;
constexpr int N_  = 64;
constexpr int LI_ = 4096;
constexpr int LT_ = 512;
constexpr int L_  = LI_ + LT_;   // 4608
constexpr int HID_ = 2048;

constexpr size_t XSZ   = (size_t)B_ * C_ * L_;      // 9.44M
constexpr size_t IMGSZ = (size_t)B_ * C_ * LI_;     // 8.39M
constexpr size_t TXTSZ = (size_t)B_ * C_ * LT_;     // 1.05M

// ---------------- scratch (static device memory; no allocations) -------------
__device__ float g_scond[B_ * C_];
__device__ float g_mod[2 * B_ * 6 * C_];            // [s][b][6C]
__device__ float g_x[XSZ];
__device__ float g_tmp[XSZ];
__device__ float g_r[XSZ];                          // (B,H,L,N)
__device__ float g_k[XSZ];
__device__ float g_v[XSZ];
__device__ float g_gate[XSZ];                       // silu(Wg @ mix) (B,C,L)
__device__ float g_y[XSZ];                          // scan out (B,H,L,N)
__device__ float g_z[XSZ];                          // gnorm*gate (B,C,L)
__device__ float g_attn[XSZ];
__device__ float g_img1[IMGSZ];
__device__ float g_txt1[TXTSZ];
__device__ float g_himg[IMGSZ];
__device__ float g_htxt[TXTSZ];
__device__ float g_midimg[(size_t)B_ * HID_ * LI_];
__device__ float g_midtxt[(size_t)B_ * HID_ * LT_];

// ---------------- small elementwise ----------------
__global__ void silu_cond_k(const float* __restrict__ cond, float* __restrict__ out) {
    int i = blockIdx.x * blockDim.x + threadIdx.x;
    if (i < B_ * C_) {
        float v = cond[i];
        out[i] = v / (1.f + expf(-v));
    }
}

// one warp per (stream, output-row); both batches at once
__global__ void mod_k(const float* __restrict__ Wimg, const float* __restrict__ bimg,
                      const float* __restrict__ Wtxt, const float* __restrict__ btxt,
                      const float* __restrict__ scond, float* __restrict__ modout) {
    int gw = (blockIdx.x * blockDim.x + threadIdx.x) >> 5;
    int lane = threadIdx.x & 31;
    if (gw >= 2 * 6 * C_) return;
    int s = gw / (6 * C_), o = gw % (6 * C_);
    const float* Wp = (s ? Wtxt : Wimg) + (size_t)o * C_;
    float a0 = 0.f, a1 = 0.f;
    for (int c = lane; c < C_; c += 32) {
        float wv = Wp[c];
        a0 += wv * scond[c];
        a1 += wv * scond[C_ + c];
    }
    #pragma unroll
    for (int off = 16; off; off >>= 1) {
        a0 += __shfl_down_sync(0xffffffffu, a0, off);
        a1 += __shfl_down_sync(0xffffffffu, a1, off);
    }
    if (lane == 0) {
        float bb = (s ? btxt : bimg)[o];
        modout[(s * B_ + 0) * 6 * C_ + o] = a0 + bb;
        modout[(s * B_ + 1) * 6 * C_ + o] = a1 + bb;
    }
}

// x[b,c,l] = rms(src)*(1+sc1)+sh1, concat img||txt along l. One thread per (b,l).
__global__ void buildx_k(const float* __restrict__ img, const float* __restrict__ txt,
                         const float* __restrict__ rmswi, const float* __restrict__ rmswt,
                         const float* __restrict__ mod, float* __restrict__ x) {
    int gid = blockIdx.x * blockDim.x + threadIdx.x;
    if (gid >= B_ * L_) return;
    int b = gid / L_, l = gid % L_;
    const float* src; const float* rw; int Ls, li, s;
    if (l < LI_) { src = img; Ls = LI_; li = l;       s = 0; rw = rmswi; }
    else         { src = txt; Ls = LT_; li = l - LI_; s = 1; rw = rmswt; }
    const float* sp = src + (size_t)b * C_ * Ls + li;
    float ss = 0.f;
    #pragma unroll 8
    for (int c = 0; c < C_; c++) {
        float v = sp[(size_t)c * Ls];
        ss += v * v;
    }
    float inv = rsqrtf(ss * (1.f / C_) + 1e-6f);
    const float* mb = mod + (s * B_ + b) * 6 * C_;
    float* xp = g_x == x ? x + (size_t)b * C_ * L_ + l : x + (size_t)b * C_ * L_ + l;
    #pragma unroll 8
    for (int c = 0; c < C_; c++) {
        float v = sp[(size_t)c * Ls];
        xp[(size_t)c * L_] = v * inv * rw[c] * (1.f + mb[C_ + c]) + mb[c];
    }
}

// ---------------- generic GEMM: Y[b,m,l] = epi( sum_c W[m,c]*X'[b,c,l] ) --------
// MIX: X' = (1-mu[c])*X[b,c,l] + mu[c]*X[b,c,l-1]  (l-1 within batch, 0 at l=0)
// EPI: 0 none, 1 silu, 2 gelu(tanh), 3 residual: resid + gate[b*6C+m]*acc
template <int EPI, bool MIX>
__global__ void __launch_bounds__(256)
gemm_k(const float* __restrict__ W, const float* __restrict__ X,
       float* __restrict__ Y, const float* __restrict__ mu,
       const float* __restrict__ resid, const float* __restrict__ gate,
       int M, int K, int Llen) {
    int b  = blockIdx.z;
    int m0 = blockIdx.y * 128;
    int l0 = blockIdx.x * 128;
    const float* Xb = X + (size_t)b * K * Llen;

    __shared__ float As[16][128];
    __shared__ float Bs[16][128];

    int tid = threadIdx.x;
    int tx = tid & 15, ty = tid >> 4;
    float acc[8][8] = {};

    for (int kt = 0; kt < K; kt += 16) {
        // A tile (W): 128 rows x 16 k, stored transposed As[k][m]
        #pragma unroll
        for (int i = 0; i < 2; i++) {
            int id = tid + i * 256;
            int row = id >> 2, c4 = (id & 3) * 4;
            float4 w4 = *(const float4*)(W + (size_t)(m0 + row) * K + kt + c4);
            As[c4 + 0][row] = w4.x;
            As[c4 + 1][row] = w4.y;
            As[c4 + 2][row] = w4.z;
            As[c4 + 3][row] = w4.w;
        }
        // B tile (X): 16 k x 128 l
        #pragma unroll
        for (int i = 0; i < 8; i++) {
            int id = tid + i * 256;
            int row = id >> 7, col = id & 127;
            int gl = l0 + col;
            const float* px = Xb + (size_t)(kt + row) * Llen + gl;
            float xv = *px;
            if (MIX) {
                float xp = (gl > 0) ? px[-1] : 0.f;
                float mm = mu[kt + row];
                xv += mm * (xp - xv);
            }
            Bs[row][col] = xv;
        }
        __syncthreads();
        #pragma unroll
        for (int k = 0; k < 16; k++) {
            float4 a0 = *(const float4*)&As[k][ty * 8];
            float4 a1 = *(const float4*)&As[k][ty * 8 + 4];
            float4 b0 = *(const float4*)&Bs[k][tx * 8];
            float4 b1 = *(const float4*)&Bs[k][tx * 8 + 4];
            float av[8] = {a0.x, a0.y, a0.z, a0.w, a1.x, a1.y, a1.z, a1.w};
            float bv[8] = {b0.x, b0.y, b0.z, b0.w, b1.x, b1.y, b1.z, b1.w};
            #pragma unroll
            for (int i = 0; i < 8; i++)
                #pragma unroll
                for (int j = 0; j < 8; j++)
                    acc[i][j] += av[i] * bv[j];
        }
        __syncthreads();
    }

    size_t yb = (size_t)b * M * Llen;
    #pragma unroll
    for (int i = 0; i < 8; i++) {
        int m = m0 + ty * 8 + i;
        float* yrow = Y + yb + (size_t)m * Llen + l0 + tx * 8;
        float out[8];
        #pragma unroll
        for (int j = 0; j < 8; j++) {
            float v = acc[i][j];
            if (EPI == 1) {
                v = v / (1.f + expf(-v));
            } else if (EPI == 2) {
                float t = 0.7978845608f * (v + 0.044715f * v * v * v);
                v = 0.5f * v * (1.f + tanhf(t));
            } else if (EPI == 3) {
                v = resid[yb + (size_t)m * Llen + l0 + tx * 8 + j] + gate[b * 6 * C_ + m] * v;
            }
            out[j] = v;
        }
        *(float4*)yrow       = make_float4(out[0], out[1], out[2], out[3]);
        *(float4*)(yrow + 4) = make_float4(out[4], out[5], out[6], out[7]);
    }
}

// ---------------- transpose (B,C,L) -> (B,H,L,N) ----------------
__global__ void transpose_heads_k(const float* __restrict__ in, float* __restrict__ out) {
    __shared__ float tile[32][33];
    int b = blockIdx.z;
    int c0 = blockIdx.y * 32;
    int l0 = blockIdx.x * 32;
    int tx = threadIdx.x, ty = threadIdx.y;
    #pragma unroll
    for (int i = 0; i < 32; i += 8)
        tile[ty + i][tx] = in[(size_t)b * C_ * L_ + (size_t)(c0 + ty + i) * L_ + l0 + tx];
    __syncthreads();
    int h = c0 >> 6, nb = c0 & 63;
    #pragma unroll
    for (int i = 0; i < 32; i += 8)
        out[((size_t)(b * H_ + h) * L_ + l0 + ty + i) * N_ + nb + tx] = tile[tx][ty + i];
}

// ---------------- RWKV sequential scan ----------------
// block = (bh, m-half): 256 threads = 32 m x 8 ngroups (8 n each), S in regs
__global__ void __launch_bounds__(256)
scan_k(const float* __restrict__ rr, const float* __restrict__ kk,
       const float* __restrict__ vv, const float* __restrict__ td,
       const float* __restrict__ tf, float* __restrict__ yy) {
    int bh = blockIdx.x >> 1;
    int mh = blockIdx.x & 1;
    int tid = threadIdx.x;
    int m = tid & 31;
    int ng = tid >> 5;
    int h = bh & (H_ - 1);
    size_t base = (size_t)bh * L_ * N_;

    __shared__ float sr[64], sk[64], sv[64], su[64];
    __shared__ float ps[256];
    __shared__ float sruk;

    if (tid < 64) su[tid] = tf[h * N_ + tid];
    float w[8], S[8];
    #pragma unroll
    for (int i = 0; i < 8; i++) {
        int n = ng * 8 + i;
        w[i] = expf(-expf(td[h * N_ + n]));
        S[i] = 0.f;
    }
    __syncthreads();

    int gm = mh * 32 + m;
    for (int l = 0; l < L_; l++) {
        size_t off = base + (size_t)l * N_;
        if (tid < 64)        sr[tid]       = rr[off + tid];
        else if (tid < 128)  sk[tid - 64]  = kk[off + tid - 64];
        else if (tid < 192)  sv[tid - 128] = vv[off + tid - 128];
        __syncthreads();

        if (tid < 32) {  // warp0: ruk = sum_n r*u*k
            float p = sr[tid] * su[tid] * sk[tid] + sr[tid + 32] * su[tid + 32] * sk[tid + 32];
            #pragma unroll
            for (int o = 16; o; o >>= 1) p += __shfl_down_sync(0xffffffffu, p, o);
            if (tid == 0) sruk = p;
        }

        float vm = sv[gm];
        float4 r0 = *(const float4*)&sr[ng * 8];
        float4 r1 = *(const float4*)&sr[ng * 8 + 4];
        float4 k0 = *(const float4*)&sk[ng * 8];
        float4 k1 = *(const float4*)&sk[ng * 8 + 4];
        float rv[8] = {r0.x, r0.y, r0.z, r0.w, r1.x, r1.y, r1.z, r1.w};
        float kv[8] = {k0.x, k0.y, k0.z, k0.w, k1.x, k1.y, k1.z, k1.w};

        float partial = 0.f;
        #pragma unroll
        for (int i = 0; i < 8; i++) {
            partial += rv[i] * S[i];
            S[i] = w[i] * S[i] + kv[i] * vm;
        }
        ps[tid] = partial;
        __syncthreads();

        if (tid < 32) {
            float y = sruk * vm;
            #pragma unroll
            for (int j = 0; j < 8; j++) y += ps[m + 32 * j];
            yy[off + gm] = y;
        }
        __syncthreads();
    }
}

// ---------------- groupnorm(y over N) * ln_x * gate, transpose to (B,C,L) ------
__global__ void __launch_bounds__(256)
gnorm_k(const float* __restrict__ yy, const float* __restrict__ gate,
        const float* __restrict__ lnw, const float* __restrict__ lnb,
        float* __restrict__ z) {
    int b = blockIdx.z, h = blockIdx.y, l0 = blockIdx.x * 64;
    __shared__ float tile[64][65];          // [n][l]
    __shared__ float rs1[4][64], rs2[4][64];
    __shared__ float smean[64], sinv[64];
    int tid = threadIdx.x;
    size_t ybase = ((size_t)(b * H_ + h) * L_ + l0) * N_;

    #pragma unroll
    for (int i = 0; i < 16; i++) {
        int id = tid + i * 256;
        int row = id >> 6;   // l
        int col = id & 63;   // n
        tile[col][row] = yy[ybase + (size_t)row * N_ + col];
    }
    __syncthreads();
    {
        int l = tid & 63, part = tid >> 6;
        float s1 = 0.f, s2 = 0.f;
        #pragma unroll
        for (int i = 0; i < 16; i++) {
            float v = tile[part * 16 + i][l];
            s1 += v; s2 += v * v;
        }
        rs1[part][l] = s1; rs2[part][l] = s2;
    }
    __syncthreads();
    if (tid < 64) {
        float s1 = rs1[0][tid] + rs1[1][tid] + rs1[2][tid] + rs1[3][tid];
        float s2 = rs2[0][tid] + rs2[1][tid] + rs2[2][tid] + rs2[3][tid];
        float mean = s1 * (1.f / 64);
        float var = s2 * (1.f / 64) - mean * mean;
        smean[tid] = mean;
        sinv[tid] = rsqrtf(var + 1e-5f);
    }
    __syncthreads();

    int n = tid >> 2, lq = tid & 3;
    int c = h * 64 + n;
    float lw = lnw[c], lb = lnb[c];
    size_t zofs = (size_t)b * C_ * L_ + (size_t)c * L_ + l0 + lq * 16;
    const float* gp = gate + zofs;
    float* zp = z + zofs;
    #pragma unroll
    for (int q = 0; q < 16; q += 4) {
        float4 o;
        float* po = &o.x;
        #pragma unroll
        for (int e = 0; e < 4; e++) {
            int l = lq * 16 + q + e;
            float v = (tile[n][l] - smean[l]) * sinv[l] * lw + lb;
            po[e] = v * gp[q + e];
        }
        *(float4*)(zp + q) = o;
    }
}

// ---------------- attn residual + rms for FFN input ----------------
__global__ void resid_rms_k(const float* __restrict__ img, const float* __restrict__ txt,
                            const float* __restrict__ attn, const float* __restrict__ mod,
                            const float* __restrict__ w2i, const float* __restrict__ w2t,
                            float* __restrict__ img1, float* __restrict__ txt1,
                            float* __restrict__ himg, float* __restrict__ htxt) {
    int gid = blockIdx.x * blockDim.x + threadIdx.x;
    if (gid >= B_ * L_) return;
    int b = gid / L_, l = gid % L_;
    int s, li, Ls;
    const float* src; float* d1; float* dh; const float* rw;
    if (l < LI_) { s = 0; li = l;       Ls = LI_; src = img; d1 = img1; dh = himg; rw = w2i; }
    else         { s = 1; li = l - LI_; Ls = LT_; src = txt; d1 = txt1; dh = htxt; rw = w2t; }
    const float* mb = mod + (s * B_ + b) * 6 * C_;
    const float* ap = attn + (size_t)b * C_ * L_ + l;
    const float* sp = src + (size_t)b * C_ * Ls + li;
    float* p1 = d1 + (size_t)b * C_ * Ls + li;
    float* ph = dh + (size_t)b * C_ * Ls + li;
    float ss = 0.f;
    #pragma unroll 8
    for (int c = 0; c < C_; c++) {
        float v = sp[(size_t)c * Ls] + mb[2 * C_ + c] * ap[(size_t)c * L_];
        p1[(size_t)c * Ls] = v;
        ss += v * v;
    }
    float inv = rsqrtf(ss * (1.f / C_) + 1e-6f);
    #pragma unroll 8
    for (int c = 0; c < C_; c++) {
        float v = p1[(size_t)c * Ls];
        ph[(size_t)c * Ls] = v * inv * rw[c] * (1.f + mb[4 * C_ + c]) + mb[3 * C_ + c];
    }
}

// ---------------- host launcher ----------------
static float* symaddr(const void* s) {
    void* p = nullptr;
    cudaGetSymbolAddress(&p, s);
    return (float*)p;
}

extern "C" void kernel_launch(void* const* d_in, const int* in_sizes, int n_in,
                              void* d_out, int out_size) {
    const float* img   = (const float*)d_in[0];
    const float* txt   = (const float*)d_in[1];
    const float* cond  = (const float*)d_in[2];
    const float* Wmi   = (const float*)d_in[3];
    const float* bmi   = (const float*)d_in[4];
    const float* Wmt   = (const float*)d_in[5];
    const float* bmt   = (const float*)d_in[6];
    const float* rmsi  = (const float*)d_in[7];
    const float* rmst  = (const float*)d_in[8];
    const float* rmsi2 = (const float*)d_in[9];
    const float* rmst2 = (const float*)d_in[10];
    const float* mur   = (const float*)d_in[11];
    const float* muk   = (const float*)d_in[12];
    const float* muv   = (const float*)d_in[13];
    const float* mug   = (const float*)d_in[14];
    const float* Wr    = (const float*)d_in[15];
    const float* Wk    = (const float*)d_in[16];
    const float* Wv    = (const float*)d_in[17];
    const float* Wg    = (const float*)d_in[18];
    const float* Wo    = (const float*)d_in[19];
    const float* td    = (const float*)d_in[20];
    const float* tf    = (const float*)d_in[21];
    const float* lnw   = (const float*)d_in[22];
    const float* lnb   = (const float*)d_in[23];
    const float* fi1   = (const float*)d_in[24];
    const float* fi2   = (const float*)d_in[25];
    const float* ft1   = (const float*)d_in[26];
    const float* ft2   = (const float*)d_in[27];

    float* p_scond = symaddr(g_scond);
    float* p_mod   = symaddr(g_mod);
    float* p_x     = symaddr(g_x);
    float* p_tmp   = symaddr(g_tmp);
    float* p_r     = symaddr(g_r);
    float* p_k     = symaddr(g_k);
    float* p_v     = symaddr(g_v);
    float* p_gate  = symaddr(g_gate);
    float* p_y     = symaddr(g_y);
    float* p_z     = symaddr(g_z);
    float* p_attn  = symaddr(g_attn);
    float* p_img1  = symaddr(g_img1);
    float* p_txt1  = symaddr(g_txt1);
    float* p_himg  = symaddr(g_himg);
    float* p_htxt  = symaddr(g_htxt);
    float* p_mi    = symaddr(g_midimg);
    float* p_mt    = symaddr(g_midtxt);

    float* out_img = (float*)d_out;
    float* out_txt = out_img + IMGSZ;

    // 1) silu(cond), modulation vectors
    silu_cond_k<<<(B_ * C_ + 255) / 256, 256>>>(cond, p_scond);
    mod_k<<<(2 * 6 * C_) / 8, 256>>>(Wmi, bmi, Wmt, bmt, p_scond, p_mod);

    // 2) x = concat(rms-mod img, rms-mod txt)
    buildx_k<<<(B_ * L_) / 256, 256>>>(img, txt, rmsi, rmst, p_mod, p_x);

    dim3 gFull(L_ / 128, C_ / 128, B_);
    dim3 gTr(L_ / 32, C_ / 32, B_);

    // 3) r,k,v with time-mix fused; transpose to heads
    gemm_k<0, true><<<gFull, 256>>>(Wr, p_x, p_tmp, mur, nullptr, nullptr, C_, C_, L_);
    transpose_heads_k<<<gTr, dim3(32, 8)>>>(p_tmp, p_r);
    gemm_k<0, true><<<gFull, 256>>>(Wk, p_x, p_tmp, muk, nullptr, nullptr, C_, C_, L_);
    transpose_heads_k<<<gTr, dim3(32, 8)>>>(p_tmp, p_k);
    gemm_k<0, true><<<gFull, 256>>>(Wv, p_x, p_tmp, muv, nullptr, nullptr, C_, C_, L_);
    transpose_heads_k<<<gTr, dim3(32, 8)>>>(p_tmp, p_v);
    // g = silu(Wg @ mix)
    gemm_k<1, true><<<gFull, 256>>>(Wg, p_x, p_gate, mug, nullptr, nullptr, C_, C_, L_);

    // 4) sequential RWKV scan
    scan_k<<<B_ * H_ * 2, 256>>>(p_r, p_k, p_v, td, tf, p_y);

    // 5) groupnorm + ln_x + gate, back to (B,C,L)
    gnorm_k<<<dim3(L_ / 64, H_, B_), 256>>>(p_y, p_gate, lnw, lnb, p_z);

    // 6) attn = Wo @ z
    gemm_k<0, false><<<gFull, 256>>>(Wo, p_z, p_attn, nullptr, nullptr, nullptr, C_, C_, L_);

    // 7) residual + rms for FFN input
    resid_rms_k<<<(B_ * L_) / 256, 256>>>(img, txt, p_attn, p_mod, rmsi2, rmst2,
                                          p_img1, p_txt1, p_himg, p_htxt);

    // 8) FFN img
    gemm_k<2, false><<<dim3(LI_ / 128, HID_ / 128, B_), 256>>>(
        fi1, p_himg, p_mi, nullptr, nullptr, nullptr, HID_, C_, LI_);
    gemm_k<3, false><<<dim3(LI_ / 128, C_ / 128, B_), 256>>>(
        fi2, p_mi, out_img, nullptr, p_img1, p_mod + 0 * B_ * 6 * C_ + 5 * C_, C_, HID_, LI_);

    // 9) FFN txt
    gemm_k<2, false><<<dim3(LT_ / 128, HID_ / 128, B_), 256>>>(
        ft1, p_htxt, p_mt, nullptr, nullptr, nullptr, HID_, C_, LT_);
    gemm_k<3, false><<<dim3(LT_ / 128, C_ / 128, B_), 256>>>(
        ft2, p_mt, out_txt, nullptr, p_txt1, p_mod + 1 * B_ * 6 * C_ + 5 * C_, C_, HID_, LT_);
}

// round 5
// speedup vs baseline: 1.2273x; 1.2273x over previous
#include <cuda_runtime.h>
#include <cuda_fp16.h>
#include <math.h>
#include <stdint.h>

constexpr int B_  = 2;
constexpr int C_  = 1024;
constexpr int H_  = 16;
constexpr int N_  = 64;
constexpr int LI_ = 4096;
constexpr int LT_ = 512;
constexpr int L_  = LI_ + LT_;   // 4608
constexpr int HID_ = 2048;

constexpr size_t XSZ   = (size_t)B_ * C_ * L_;
constexpr size_t IMGSZ = (size_t)B_ * C_ * LI_;
constexpr size_t TXTSZ = (size_t)B_ * C_ * LT_;

// ---------------- static scratch ----------------
__device__ float g_scond[B_ * C_];
__device__ float g_mod[2 * B_ * 6 * C_];
__device__ float g_x[XSZ];
__device__ float g_rkvg[(size_t)B_ * 4 * C_ * L_];   // fused r|k|v|silu(g)
__device__ float g_r[XSZ];
__device__ float g_k[XSZ];
__device__ float g_v[XSZ];
__device__ float g_y[XSZ];
__device__ float g_z[XSZ];
__device__ float g_attn[XSZ];
__device__ float g_img1[IMGSZ];
__device__ float g_txt1[TXTSZ];
__device__ float g_himg[IMGSZ];
__device__ float g_htxt[TXTSZ];
__device__ float g_midimg[(size_t)B_ * HID_ * LI_];
__device__ float g_midtxt[(size_t)B_ * HID_ * LT_];

__device__ __half g_Arkvg[(size_t)4096 * 6144];
__device__ __half g_Awo [(size_t)1024 * 3072];
__device__ __half g_Afi1[(size_t)2048 * 3072];
__device__ __half g_Afi2[(size_t)1024 * 6144];
__device__ __half g_Aft1[(size_t)2048 * 3072];
__device__ __half g_Aft2[(size_t)1024 * 6144];
__device__ __half g_Bx [(size_t)B_ * L_  * 6144];
__device__ __half g_Bz [(size_t)B_ * L_  * 3072];
__device__ __half g_Bhi[(size_t)B_ * LI_ * 3072];
__device__ __half g_Bht[(size_t)B_ * LT_ * 3072];
__device__ __half g_Bmi[(size_t)B_ * LI_ * 6144];
__device__ __half g_Bmt[(size_t)B_ * LT_ * 6144];

// ---------------- helpers ----------------
__device__ __forceinline__ uint32_t smem_u32(const void* p) {
    uint32_t r;
    asm("{ .reg .u64 t; cvta.to.shared.u64 t, %1; cvt.u32.u64 %0, t; }" : "=r"(r) : "l"(p));
    return r;
}
__device__ __forceinline__ void cp16(uint32_t s, const void* g) {
    asm volatile("cp.async.cg.shared.global [%0], [%1], 16;" :: "r"(s), "l"(g));
}
__device__ __forceinline__ void ldsm4(uint32_t* r, uint32_t addr) {
    asm volatile("ldmatrix.sync.aligned.m8n8.x4.shared.b16 {%0,%1,%2,%3},[%4];"
                 : "=r"(r[0]), "=r"(r[1]), "=r"(r[2]), "=r"(r[3]) : "r"(addr));
}
__device__ __forceinline__ void mma16816(float* d, const uint32_t* a, const uint32_t* b) {
    asm volatile("mma.sync.aligned.m16n8k16.row.col.f32.f16.f16.f32 "
                 "{%0,%1,%2,%3},{%4,%5,%6,%7},{%8,%9},{%0,%1,%2,%3};"
                 : "+f"(d[0]), "+f"(d[1]), "+f"(d[2]), "+f"(d[3])
                 : "r"(a[0]), "r"(a[1]), "r"(a[2]), "r"(a[3]), "r"(b[0]), "r"(b[1]));
}
__device__ __forceinline__ void split_f16(float v, __half& hi, __half& lo) {
    hi = __float2half(v);
    lo = __float2half(v - __half2float(hi));
}

// ---------------- small elementwise ----------------
__global__ void silu_cond_k(const float* __restrict__ cond, float* __restrict__ out) {
    int i = blockIdx.x * blockDim.x + threadIdx.x;
    if (i < B_ * C_) { float v = cond[i]; out[i] = v / (1.f + expf(-v)); }
}

__global__ void mod_k(const float* __restrict__ Wimg, const float* __restrict__ bimg,
                      const float* __restrict__ Wtxt, const float* __restrict__ btxt,
                      const float* __restrict__ scond, float* __restrict__ modout) {
    int gw = (blockIdx.x * blockDim.x + threadIdx.x) >> 5;
    int lane = threadIdx.x & 31;
    if (gw >= 2 * 6 * C_) return;
    int s = gw / (6 * C_), o = gw % (6 * C_);
    const float* Wp = (s ? Wtxt : Wimg) + (size_t)o * C_;
    float a0 = 0.f, a1 = 0.f;
    for (int c = lane; c < C_; c += 32) {
        float wv = Wp[c];
        a0 += wv * scond[c];
        a1 += wv * scond[C_ + c];
    }
    #pragma unroll
    for (int off = 16; off; off >>= 1) {
        a0 += __shfl_down_sync(0xffffffffu, a0, off);
        a1 += __shfl_down_sync(0xffffffffu, a1, off);
    }
    if (lane == 0) {
        float bb = (s ? btxt : bimg)[o];
        modout[(s * B_ + 0) * 6 * C_ + o] = a0 + bb;
        modout[(s * B_ + 1) * 6 * C_ + o] = a1 + bb;
    }
}

__global__ void __launch_bounds__(128)
buildx_k(const float* __restrict__ img, const float* __restrict__ txt,
         const float* __restrict__ rmswi, const float* __restrict__ rmswt,
         const float* __restrict__ mod, float* __restrict__ x) {
    int b = blockIdx.y;
    int l = blockIdx.x * 128 + threadIdx.x;
    const float* src; const float* rw; int Ls, li, s;
    if (l < LI_) { src = img; Ls = LI_; li = l;       s = 0; rw = rmswi; }
    else         { src = txt; Ls = LT_; li = l - LI_; s = 1; rw = rmswt; }
    const float* sp = src + (size_t)b * C_ * Ls + li;
    float ss = 0.f;
    #pragma unroll 8
    for (int c = 0; c < C_; c++) { float v = sp[(size_t)c * Ls]; ss += v * v; }
    float inv = rsqrtf(ss * (1.f / C_) + 1e-6f);
    const float* mb = mod + (s * B_ + b) * 6 * C_;
    float* xp = x + (size_t)b * C_ * L_ + l;
    #pragma unroll 8
    for (int c = 0; c < C_; c++) {
        float v = sp[(size_t)c * Ls];
        xp[(size_t)c * L_] = v * inv * rw[c] * (1.f + mb[C_ + c]) + mb[c];
    }
}

// ---------------- weight split preps ----------------
// rkvg: A[4096][6144] K-blocks [Wd_hi, Wd_hi, Wd_lo, Ws_hi, Ws_hi, Ws_lo]
__global__ void wsplit_rkvg_k(const float* __restrict__ Wr, const float* __restrict__ Wk,
                              const float* __restrict__ Wv, const float* __restrict__ Wg,
                              const float* __restrict__ mur, const float* __restrict__ muk,
                              const float* __restrict__ muv, const float* __restrict__ mug,
                              __half* __restrict__ A) {
    size_t idx = (size_t)blockIdx.x * 256 + threadIdx.x;
    if (idx >= (size_t)4096 * 1024) return;
    int m = (int)(idx >> 10), c = (int)(idx & 1023);
    int p = m >> 10, mr = m & 1023;
    const float* W = (p == 0) ? Wr : (p == 1) ? Wk : (p == 2) ? Wv : Wg;
    const float* mu = (p == 0) ? mur : (p == 1) ? muk : (p == 2) ? muv : mug;
    float mm = mu[c];
    float wv = W[(size_t)mr * C_ + c];
    float wd = wv * (1.f - mm), ws = wv * mm;
    __half dh, dl, sh, sl;
    split_f16(wd, dh, dl); split_f16(ws, sh, sl);
    __half* o = A + (size_t)m * 6144 + c;
    o[0] = dh; o[1024] = dh; o[2048] = dl;
    o[3072] = sh; o[4096] = sh; o[5120] = sl;
}

// plain: W (M,K) -> A (M,3K) K-blocks [hi, hi, lo]
__global__ void wsplit_plain_k(const float* __restrict__ W, __half* __restrict__ A,
                               int M, int K) {
    size_t idx = (size_t)blockIdx.x * 256 + threadIdx.x;
    if (idx >= (size_t)M * K) return;
    int m = (int)(idx / K), k = (int)(idx % K);
    __half hi, lo; split_f16(W[idx], hi, lo);
    __half* o = A + (size_t)m * 3 * K + k;
    o[0] = hi; o[K] = hi; o[2 * K] = lo;
}

// ---------------- activation split preps ----------------
// (B,CR,LL) fp32 -> (B,LL,3CR) K-blocks [hi, lo, hi]
__global__ void __launch_bounds__(256)
asplit_k(const float* __restrict__ in, __half* __restrict__ out, int CR, int LL) {
    __shared__ float tile[32][33];
    int b = blockIdx.z, c0 = blockIdx.y * 32, l0 = blockIdx.x * 32;
    int tx = threadIdx.x & 31, wy = threadIdx.x >> 5;
    const float* ip = in + ((size_t)b * CR + c0) * LL + l0;
    #pragma unroll
    for (int i = 0; i < 4; i++) { int c = wy + i * 8; tile[c][tx] = ip[(size_t)c * LL + tx]; }
    __syncthreads();
    int K3 = 3 * CR;
    #pragma unroll
    for (int i = 0; i < 4; i++) {
        int l = wy + i * 8;
        __half hi, lo; split_f16(tile[tx][l], hi, lo);
        __half* op = out + ((size_t)b * LL + l0 + l) * K3 + (c0 + tx);
        op[0] = hi; op[CR] = lo; op[2 * CR] = hi;
    }
}

// x (B,C,L) -> Bx (B,L,6144): direct [hi,lo,hi] at [0,3072), shifted copy at row l+1 [3072,6144)
__global__ void __launch_bounds__(256)
asplit_shift_k(const float* __restrict__ x, __half* __restrict__ out) {
    __shared__ float tile[32][33];
    int b = blockIdx.z, c0 = blockIdx.y * 32, l0 = blockIdx.x * 32;
    int tx = threadIdx.x & 31, wy = threadIdx.x >> 5;
    const float* ip = x + ((size_t)b * C_ + c0) * L_ + l0;
    #pragma unroll
    for (int i = 0; i < 4; i++) { int c = wy + i * 8; tile[c][tx] = ip[(size_t)c * L_ + tx]; }
    __syncthreads();
    #pragma unroll
    for (int i = 0; i < 4; i++) {
        int l = l0 + wy + i * 8;
        __half hi, lo; split_f16(tile[tx][wy + i * 8], hi, lo);
        __half* op = out + ((size_t)b * L_ + l) * 6144 + (c0 + tx);
        op[0] = hi; op[1024] = lo; op[2048] = hi;
        if (l + 1 < L_) {
            __half* os = out + ((size_t)b * L_ + l + 1) * 6144 + 3072 + (c0 + tx);
            os[0] = hi; os[1024] = lo; os[2048] = hi;
        }
        if (l == 0) {
            __half z = __float2half(0.f);
            __half* os = out + ((size_t)b * L_) * 6144 + 3072 + (c0 + tx);
            os[0] = z; os[1024] = z; os[2048] = z;
        }
    }
}

// ---------------- mma.sync GEMM ----------------
// D[b, m0+0:128, l0+0:128] = epi( A[m,:K3] . B[b,l,:K3] )
// MODE 0 plain, 1 rkvg (silu rows >= 3C), 2 gelu, 3 resid + gate
template <int MODE>
__global__ void __launch_bounds__(256, 1)
gemm_mma(const __half* __restrict__ A, const __half* __restrict__ Bm,
         float* __restrict__ Y, const float* __restrict__ resid,
         const float* __restrict__ gmod, int M, int K3, int Llen) {
    __shared__ __align__(16) __half sA[2][128 * 40];
    __shared__ __align__(16) __half sB[2][128 * 40];
    int tid = threadIdx.x, lane = tid & 31, wid = tid >> 5;
    int wm = wid >> 2, wn = wid & 3;
    int b = blockIdx.z, l0 = blockIdx.x * 128, m0 = blockIdx.y * 128;
    const int NT = K3 >> 5;

    float acc[4][4][4] = {};
    uint32_t sA0 = smem_u32(sA), sB0 = smem_u32(sB);
    const __half* Ag = A + (size_t)m0 * K3;
    const __half* Bg = Bm + ((size_t)b * Llen + l0) * K3;

    int r_ld = tid >> 1, ch_ld = (tid & 1) * 2;   // each thread: 2 chunks in one row

    // prologue: tile 0
    {
        uint32_t so = (uint32_t)(r_ld * 80 + ch_ld * 16);
        cp16(sA0 + so,      Ag + (size_t)r_ld * K3 + ch_ld * 8);
        cp16(sA0 + so + 16, Ag + (size_t)r_ld * K3 + ch_ld * 8 + 8);
        cp16(sB0 + so,      Bg + (size_t)r_ld * K3 + ch_ld * 8);
        cp16(sB0 + so + 16, Bg + (size_t)r_ld * K3 + ch_ld * 8 + 8);
        asm volatile("cp.async.commit_group;");
    }

    for (int it = 0; it < NT; it++) {
        int q = it & 1;
        if (it + 1 < NT) {
            int qq = q ^ 1;
            uint32_t so = (uint32_t)(qq * 10240 + r_ld * 80 + ch_ld * 16);
            size_t ko = (size_t)(it + 1) * 32 + ch_ld * 8;
            cp16(sA0 + so,      Ag + (size_t)r_ld * K3 + ko);
            cp16(sA0 + so + 16, Ag + (size_t)r_ld * K3 + ko + 8);
            cp16(sB0 + so,      Bg + (size_t)r_ld * K3 + ko);
            cp16(sB0 + so + 16, Bg + (size_t)r_ld * K3 + ko + 8);
            asm volatile("cp.async.commit_group;");
            asm volatile("cp.async.wait_group 1;");
        } else {
            asm volatile("cp.async.wait_group 0;");
        }
        __syncthreads();

        uint32_t baseA = sA0 + q * 10240, baseB = sB0 + q * 10240;
        #pragma unroll
        for (int kk = 0; kk < 2; kk++) {
            uint32_t a[4][4], bq[2][4];
            #pragma unroll
            for (int ma = 0; ma < 4; ma++)
                ldsm4(a[ma], baseA + (wm * 64 + ma * 16 + (lane & 15)) * 80
                              + kk * 32 + (lane >> 4) * 16);
            #pragma unroll
            for (int nb = 0; nb < 2; nb++)
                ldsm4(bq[nb], baseB + (wn * 32 + nb * 16 + (lane & 7) + ((lane >> 4) & 1) * 8) * 80
                               + kk * 32 + ((lane >> 3) & 1) * 16);
            #pragma unroll
            for (int ma = 0; ma < 4; ma++)
                #pragma unroll
                for (int na = 0; na < 4; na++)
                    mma16816(acc[ma][na], a[ma], &bq[na >> 1][(na & 1) * 2]);
        }
        __syncthreads();
    }

    // epilogue
    #pragma unroll
    for (int ma = 0; ma < 4; ma++) {
        #pragma unroll
        for (int hf = 0; hf < 2; hf++) {
            int m = m0 + wm * 64 + ma * 16 + (lane >> 2) + hf * 8;
            size_t ybase = ((size_t)b * M + m) * Llen;
            float gm;
            if (MODE == 3) gm = gmod[b * 6 * C_ + m];
            #pragma unroll
            for (int na = 0; na < 4; na++) {
                int col = l0 + wn * 32 + na * 8 + 2 * (lane & 3);
                float v0 = acc[ma][na][hf * 2], v1 = acc[ma][na][hf * 2 + 1];
                if (MODE == 1) {
                    if (m >= 3 * C_) {
                        v0 = v0 / (1.f + expf(-v0));
                        v1 = v1 / (1.f + expf(-v1));
                    }
                } else if (MODE == 2) {
                    float t0 = 0.7978845608f * (v0 + 0.044715f * v0 * v0 * v0);
                    v0 = 0.5f * v0 * (1.f + tanhf(t0));
                    float t1 = 0.7978845608f * (v1 + 0.044715f * v1 * v1 * v1);
                    v1 = 0.5f * v1 * (1.f + tanhf(t1));
                } else if (MODE == 3) {
                    float2 rr = *(const float2*)(resid + ybase + col);
                    v0 = rr.x + gm * v0;
                    v1 = rr.y + gm * v1;
                }
                *(float2*)(Y + ybase + col) = make_float2(v0, v1);
            }
        }
    }
}

// ---------------- transpose slice of (B,4C,L) -> (B,H,L,N) ----------------
__global__ void transpose_heads_k(const float* __restrict__ in, float* __restrict__ out,
                                  size_t bstride) {
    __shared__ float tile[32][33];
    int b = blockIdx.z, c0 = blockIdx.y * 32, l0 = blockIdx.x * 32;
    int tx = threadIdx.x, ty = threadIdx.y;
    #pragma unroll
    for (int i = 0; i < 32; i += 8)
        tile[ty + i][tx] = in[(size_t)b * bstride + (size_t)(c0 + ty + i) * L_ + l0 + tx];
    __syncthreads();
    int h = c0 >> 6, nb = c0 & 63;
    #pragma unroll
    for (int i = 0; i < 32; i += 8)
        out[((size_t)(b * H_ + h) * L_ + l0 + ty + i) * N_ + nb + tx] = tile[tx][ty + i];
}

// ---------------- RWKV scan ----------------
__global__ void __launch_bounds__(256)
scan_k(const float* __restrict__ rr, const float* __restrict__ kk,
       const float* __restrict__ vv, const float* __restrict__ td,
       const float* __restrict__ tf, float* __restrict__ yy) {
    int bh = blockIdx.x >> 1;
    int mh = blockIdx.x & 1;
    int tid = threadIdx.x;
    int m = tid & 31, ng = tid >> 5;
    int h = bh & (H_ - 1);
    size_t base = (size_t)bh * L_ * N_;

    __shared__ float sr[64], sk[64], sv[64], su[64];
    __shared__ float ps[256];
    __shared__ float sruk;

    if (tid < 64) su[tid] = tf[h * N_ + tid];
    float w[8], S[8];
    #pragma unroll
    for (int i = 0; i < 8; i++) {
        int n = ng * 8 + i;
        w[i] = expf(-expf(td[h * N_ + n]));
        S[i] = 0.f;
    }
    __syncthreads();

    int gm = mh * 32 + m;
    for (int l = 0; l < L_; l++) {
        size_t off = base + (size_t)l * N_;
        if (tid < 64)        sr[tid]       = rr[off + tid];
        else if (tid < 128)  sk[tid - 64]  = kk[off + tid - 64];
        else if (tid < 192)  sv[tid - 128] = vv[off + tid - 128];
        __syncthreads();

        if (tid < 32) {
            float p = sr[tid] * su[tid] * sk[tid] + sr[tid + 32] * su[tid + 32] * sk[tid + 32];
            #pragma unroll
            for (int o = 16; o; o >>= 1) p += __shfl_down_sync(0xffffffffu, p, o);
            if (tid == 0) sruk = p;
        }

        float vm = sv[gm];
        float4 r0 = *(const float4*)&sr[ng * 8];
        float4 r1 = *(const float4*)&sr[ng * 8 + 4];
        float4 k0 = *(const float4*)&sk[ng * 8];
        float4 k1 = *(const float4*)&sk[ng * 8 + 4];
        float rv[8] = {r0.x, r0.y, r0.z, r0.w, r1.x, r1.y, r1.z, r1.w};
        float kv[8] = {k0.x, k0.y, k0.z, k0.w, k1.x, k1.y, k1.z, k1.w};

        float partial = 0.f;
        #pragma unroll
        for (int i = 0; i < 8; i++) {
            partial += rv[i] * S[i];
            S[i] = w[i] * S[i] + kv[i] * vm;
        }
        ps[tid] = partial;
        __syncthreads();

        if (tid < 32) {
            float y = sruk * vm;
            #pragma unroll
            for (int j = 0; j < 8; j++) y += ps[m + 32 * j];
            yy[off + gm] = y;
        }
        __syncthreads();
    }
}

// ---------------- groupnorm * ln_x * gate -> (B,C,L) ----------------
__global__ void __launch_bounds__(256)
gnorm_k(const float* __restrict__ yy, const float* __restrict__ gate, size_t gbstride,
        const float* __restrict__ lnw, const float* __restrict__ lnb,
        float* __restrict__ z) {
    int b = blockIdx.z, h = blockIdx.y, l0 = blockIdx.x * 64;
    __shared__ float tile[64][65];
    __shared__ float rs1[4][64], rs2[4][64];
    __shared__ float smean[64], sinv[64];
    int tid = threadIdx.x;
    size_t ybase = ((size_t)(b * H_ + h) * L_ + l0) * N_;

    #pragma unroll
    for (int i = 0; i < 16; i++) {
        int id = tid + i * 256;
        int row = id >> 6, col = id & 63;
        tile[col][row] = yy[ybase + (size_t)row * N_ + col];
    }
    __syncthreads();
    {
        int l = tid & 63, part = tid >> 6;
        float s1 = 0.f, s2 = 0.f;
        #pragma unroll
        for (int i = 0; i < 16; i++) {
            float v = tile[part * 16 + i][l];
            s1 += v; s2 += v * v;
        }
        rs1[part][l] = s1; rs2[part][l] = s2;
    }
    __syncthreads();
    if (tid < 64) {
        float s1 = rs1[0][tid] + rs1[1][tid] + rs1[2][tid] + rs1[3][tid];
        float s2 = rs2[0][tid] + rs2[1][tid] + rs2[2][tid] + rs2[3][tid];
        float mean = s1 * (1.f / 64);
        float var = s2 * (1.f / 64) - mean * mean;
        smean[tid] = mean;
        sinv[tid] = rsqrtf(var + 1e-5f);
    }
    __syncthreads();

    int n = tid >> 2, lq = tid & 3;
    int c = h * 64 + n;
    float lw = lnw[c], lb = lnb[c];
    size_t zofs = (size_t)b * C_ * L_ + (size_t)c * L_ + l0 + lq * 16;
    size_t gofs = (size_t)b * gbstride + (size_t)c * L_ + l0 + lq * 16;
    const float* gp = gate + gofs;
    float* zp = z + zofs;
    #pragma unroll
    for (int q = 0; q < 16; q += 4) {
        float4 o;
        float* po = &o.x;
        #pragma unroll
        for (int e = 0; e < 4; e++) {
            int l = lq * 16 + q + e;
            po[e] = ((tile[n][l] - smean[l]) * sinv[l] * lw + lb) * gp[q + e];
        }
        *(float4*)(zp + q) = o;
    }
}

// ---------------- residual + rms (block per 128 l) ----------------
__global__ void __launch_bounds__(128)
resid_rms_k(const float* __restrict__ img, const float* __restrict__ txt,
            const float* __restrict__ attn, const float* __restrict__ mod,
            const float* __restrict__ w2i, const float* __restrict__ w2t,
            float* __restrict__ img1, float* __restrict__ txt1,
            float* __restrict__ himg, float* __restrict__ htxt) {
    int b = blockIdx.y;
    int l = blockIdx.x * 128 + threadIdx.x;
    int s, li, Ls;
    const float* src; float* d1; float* dh; const float* rw;
    if (l < LI_) { s = 0; li = l;       Ls = LI_; src = img; d1 = img1; dh = himg; rw = w2i; }
    else         { s = 1; li = l - LI_; Ls = LT_; src = txt; d1 = txt1; dh = htxt; rw = w2t; }
    const float* mb = mod + (s * B_ + b) * 6 * C_;
    const float* ap = attn + (size_t)b * C_ * L_ + l;
    const float* sp = src + (size_t)b * C_ * Ls + li;
    float* p1 = d1 + (size_t)b * C_ * Ls + li;
    float* ph = dh + (size_t)b * C_ * Ls + li;
    float ss = 0.f;
    #pragma unroll 4
    for (int c = 0; c < C_; c++) {
        float v = sp[(size_t)c * Ls] + mb[2 * C_ + c] * ap[(size_t)c * L_];
        p1[(size_t)c * Ls] = v;
        ss += v * v;
    }
    float inv = rsqrtf(ss * (1.f / C_) + 1e-6f);
    #pragma unroll 4
    for (int c = 0; c < C_; c++) {
        float v = p1[(size_t)c * Ls];
        ph[(size_t)c * Ls] = v * inv * rw[c] * (1.f + mb[4 * C_ + c]) + mb[3 * C_ + c];
    }
}

// ---------------- host ----------------
static float* symaddr(const void* s) {
    void* p = nullptr;
    cudaGetSymbolAddress(&p, s);
    return (float*)p;
}
static __half* symaddrh(const void* s) {
    void* p = nullptr;
    cudaGetSymbolAddress(&p, s);
    return (__half*)p;
}

extern "C" void kernel_launch(void* const* d_in, const int* in_sizes, int n_in,
                              void* d_out, int out_size) {
    const float* img   = (const float*)d_in[0];
    const float* txt   = (const float*)d_in[1];
    const float* cond  = (const float*)d_in[2];
    const float* Wmi   = (const float*)d_in[3];
    const float* bmi   = (const float*)d_in[4];
    const float* Wmt   = (const float*)d_in[5];
    const float* bmt   = (const float*)d_in[6];
    const float* rmsi  = (const float*)d_in[7];
    const float* rmst  = (const float*)d_in[8];
    const float* rmsi2 = (const float*)d_in[9];
    const float* rmst2 = (const float*)d_in[10];
    const float* mur   = (const float*)d_in[11];
    const float* muk   = (const float*)d_in[12];
    const float* muv   = (const float*)d_in[13];
    const float* mug   = (const float*)d_in[14];
    const float* Wr    = (const float*)d_in[15];
    const float* Wk    = (const float*)d_in[16];
    const float* Wv    = (const float*)d_in[17];
    const float* Wg    = (const float*)d_in[18];
    const float* Wo    = (const float*)d_in[19];
    const float* td    = (const float*)d_in[20];
    const float* tf    = (const float*)d_in[21];
    const float* lnw   = (const float*)d_in[22];
    const float* lnb   = (const float*)d_in[23];
    const float* fi1   = (const float*)d_in[24];
    const float* fi2   = (const float*)d_in[25];
    const float* ft1   = (const float*)d_in[26];
    const float* ft2   = (const float*)d_in[27];

    float* p_scond = symaddr(g_scond);
    float* p_mod   = symaddr(g_mod);
    float* p_x     = symaddr(g_x);
    float* p_rkvg  = symaddr(g_rkvg);
    float* p_r     = symaddr(g_r);
    float* p_k     = symaddr(g_k);
    float* p_v     = symaddr(g_v);
    float* p_y     = symaddr(g_y);
    float* p_z     = symaddr(g_z);
    float* p_attn  = symaddr(g_attn);
    float* p_img1  = symaddr(g_img1);
    float* p_txt1  = symaddr(g_txt1);
    float* p_himg  = symaddr(g_himg);
    float* p_htxt  = symaddr(g_htxt);
    float* p_mi    = symaddr(g_midimg);
    float* p_mt    = symaddr(g_midtxt);

    __half* pArkvg = symaddrh(g_Arkvg);
    __half* pAwo   = symaddrh(g_Awo);
    __half* pAfi1  = symaddrh(g_Afi1);
    __half* pAfi2  = symaddrh(g_Afi2);
    __half* pAft1  = symaddrh(g_Aft1);
    __half* pAft2  = symaddrh(g_Aft2);
    __half* pBx    = symaddrh(g_Bx);
    __half* pBz    = symaddrh(g_Bz);
    __half* pBhi   = symaddrh(g_Bhi);
    __half* pBht   = symaddrh(g_Bht);
    __half* pBmi   = symaddrh(g_Bmi);
    __half* pBmt   = symaddrh(g_Bmt);

    float* out_img = (float*)d_out;
    float* out_txt = out_img + IMGSZ;

    // 1) modulation
    silu_cond_k<<<(B_ * C_ + 255) / 256, 256>>>(cond, p_scond);
    mod_k<<<(2 * 6 * C_) / 8, 256>>>(Wmi, bmi, Wmt, bmt, p_scond, p_mod);

    // 2) weight splits
    wsplit_rkvg_k<<<(4096 * 1024) / 256, 256>>>(Wr, Wk, Wv, Wg, mur, muk, muv, mug, pArkvg);
    wsplit_plain_k<<<(1024 * 1024) / 256, 256>>>(Wo,  pAwo,  1024, 1024);
    wsplit_plain_k<<<(2048 * 1024) / 256, 256>>>(fi1, pAfi1, 2048, 1024);
    wsplit_plain_k<<<(1024 * 2048) / 256, 256>>>(fi2, pAfi2, 1024, 2048);
    wsplit_plain_k<<<(2048 * 1024) / 256, 256>>>(ft1, pAft1, 2048, 1024);
    wsplit_plain_k<<<(1024 * 2048) / 256, 256>>>(ft2, pAft2, 1024, 2048);

    // 3) x, split with shift
    buildx_k<<<dim3(L_ / 128, B_), 128>>>(img, txt, rmsi, rmst, p_mod, p_x);
    asplit_shift_k<<<dim3(L_ / 32, C_ / 32, B_), 256>>>(p_x, pBx);

    // 4) fused rkvg GEMM (silu on gate quarter)
    gemm_mma<1><<<dim3(L_ / 128, 4096 / 128, B_), 256>>>(
        pArkvg, pBx, p_rkvg, nullptr, nullptr, 4096, 6144, L_);

    // 5) heads transpose
    dim3 gTr(L_ / 32, C_ / 32, B_);
    size_t bs4 = (size_t)4 * C_ * L_;
    transpose_heads_k<<<gTr, dim3(32, 8)>>>(p_rkvg,                        p_r, bs4);
    transpose_heads_k<<<gTr, dim3(32, 8)>>>(p_rkvg + (size_t)C_ * L_,      p_k, bs4);
    transpose_heads_k<<<gTr, dim3(32, 8)>>>(p_rkvg + (size_t)2 * C_ * L_,  p_v, bs4);

    // 6) scan
    scan_k<<<B_ * H_ * 2, 256>>>(p_r, p_k, p_v, td, tf, p_y);

    // 7) groupnorm * gate
    gnorm_k<<<dim3(L_ / 64, H_, B_), 256>>>(p_y, p_rkvg + (size_t)3 * C_ * L_, bs4,
                                            lnw, lnb, p_z);

    // 8) Wo GEMM
    asplit_k<<<dim3(L_ / 32, C_ / 32, B_), 256>>>(p_z, pBz, C_, L_);
    gemm_mma<0><<<dim3(L_ / 128, C_ / 128, B_), 256>>>(
        pAwo, pBz, p_attn, nullptr, nullptr, C_, 3072, L_);

    // 9) residual + rms
    resid_rms_k<<<dim3(L_ / 128, B_), 128>>>(img, txt, p_attn, p_mod, rmsi2, rmst2,
                                             p_img1, p_txt1, p_himg, p_htxt);

    // 10) FFN img
    asplit_k<<<dim3(LI_ / 32, C_ / 32, B_), 256>>>(p_himg, pBhi, C_, LI_);
    gemm_mma<2><<<dim3(LI_ / 128, HID_ / 128, B_), 256>>>(
        pAfi1, pBhi, p_mi, nullptr, nullptr, HID_, 3072, LI_);
    asplit_k<<<dim3(LI_ / 32, HID_ / 32, B_), 256>>>(p_mi, pBmi, HID_, LI_);
    gemm_mma<3><<<dim3(LI_ / 128, C_ / 128, B_), 256>>>(
        pAfi2, pBmi, out_img, p_img1, p_mod + 5 * C_, C_, 6144, LI_);

    // 11) FFN txt
    asplit_k<<<dim3(LT_ / 32, C_ / 32, B_), 256>>>(p_htxt, pBht, C_, LT_);
    gemm_mma<2><<<dim3(LT_ / 128, HID_ / 128, B_), 256>>>(
        pAft1, pBht, p_mt, nullptr, nullptr, HID_, 3072, LT_);
    asplit_k<<<dim3(LT_ / 32, HID_ / 32, B_), 256>>>(p_mt, pBmt, HID_, LT_);
    gemm_mma<3><<<dim3(LT_ / 128, C_ / 128, B_), 256>>>(
        pAft2, pBmt, out_txt, p_txt1, p_mod + B_ * 6 * C_ + 5 * C_, C_, 6144, LT_);
}

// round 7
// speedup vs baseline: 1.5713x; 1.2804x over previous
#include <cuda_runtime.h>
#include <cuda_fp16.h>
#include <math.h>
#include <stdint.h>

constexpr int B_  = 2;
constexpr int C_  = 1024;
constexpr int H_  = 16;
constexpr int N_  = 64;
constexpr int LI_ = 4096;
constexpr int LT_ = 512;
constexpr int L_  = LI_ + LT_;   // 4608
constexpr int HID_ = 2048;

constexpr size_t XSZ   = (size_t)B_ * C_ * L_;
constexpr size_t IMGSZ = (size_t)B_ * C_ * LI_;
constexpr size_t TXTSZ = (size_t)B_ * C_ * LT_;

// ---------------- static scratch ----------------
__device__ float g_scond[B_ * C_];
__device__ float g_mod[2 * B_ * 6 * C_];
__device__ float g_x[XSZ];
__device__ float g_gate[XSZ];                        // silu(g) in (B,L,C)
__device__ float g_r[XSZ];                           // (B,H,L,N)
__device__ float g_k[XSZ];
__device__ float g_v[XSZ];
__device__ float g_y[XSZ];
__device__ float g_attn[XSZ];                        // (B,C,L)
__device__ float g_img1[IMGSZ];
__device__ float g_txt1[TXTSZ];
__device__ float g_himg[IMGSZ];
__device__ float g_htxt[TXTSZ];

// fp16 GEMM operands (A = [hi | lo] 2K blocks; B = single fp16)
__device__ __half g_Arkvg[(size_t)4096 * 4096];
__device__ __half g_Awo [(size_t)1024 * 2048];
__device__ __half g_Afi1[(size_t)2048 * 2048];
__device__ __half g_Afi2[(size_t)1024 * 4096];
__device__ __half g_Aft1[(size_t)2048 * 2048];
__device__ __half g_Aft2[(size_t)1024 * 4096];
__device__ __half g_Bx [(size_t)B_ * L_  * 2048];    // [x_l | x_{l-1}]
__device__ __half g_Bz [(size_t)B_ * L_  * 1024];
__device__ __half g_Bhi[(size_t)B_ * LI_ * 1024];
__device__ __half g_Bht[(size_t)B_ * LT_ * 1024];
__device__ __half g_Bmi[(size_t)B_ * LI_ * 2048];    // ffn1 img out (fp16, direct)
__device__ __half g_Bmt[(size_t)B_ * LT_ * 2048];

// ---------------- helpers ----------------
__device__ __forceinline__ uint32_t smem_u32(const void* p) {
    uint32_t r;
    asm("{ .reg .u64 t; cvta.to.shared.u64 t, %1; cvt.u32.u64 %0, t; }" : "=r"(r) : "l"(p));
    return r;
}
__device__ __forceinline__ void cp16(uint32_t s, const void* g) {
    asm volatile("cp.async.cg.shared.global [%0], [%1], 16;" :: "r"(s), "l"(g));
}
__device__ __forceinline__ void ldsm4(uint32_t* r, uint32_t addr) {
    asm volatile("ldmatrix.sync.aligned.m8n8.x4.shared.b16 {%0,%1,%2,%3},[%4];"
                 : "=r"(r[0]), "=r"(r[1]), "=r"(r[2]), "=r"(r[3]) : "r"(addr));
}
__device__ __forceinline__ void mma16816(float* d, const uint32_t* a, const uint32_t* b) {
    asm volatile("mma.sync.aligned.m16n8k16.row.col.f32.f16.f16.f32 "
                 "{%0,%1,%2,%3},{%4,%5,%6,%7},{%8,%9},{%0,%1,%2,%3};"
                 : "+f"(d[0]), "+f"(d[1]), "+f"(d[2]), "+f"(d[3])
                 : "r"(a[0]), "r"(a[1]), "r"(a[2]), "r"(a[3]), "r"(b[0]), "r"(b[1]));
}
__device__ __forceinline__ void split_f16(float v, __half& hi, __half& lo) {
    hi = __float2half(v);
    lo = __float2half(v - __half2float(hi));
}

// ---------------- small elementwise ----------------
__global__ void silu_cond_k(const float* __restrict__ cond, float* __restrict__ out) {
    int i = blockIdx.x * blockDim.x + threadIdx.x;
    if (i < B_ * C_) { float v = cond[i]; out[i] = v / (1.f + expf(-v)); }
}

__global__ void mod_k(const float* __restrict__ Wimg, const float* __restrict__ bimg,
                      const float* __restrict__ Wtxt, const float* __restrict__ btxt,
                      const float* __restrict__ scond, float* __restrict__ modout) {
    int gw = (blockIdx.x * blockDim.x + threadIdx.x) >> 5;
    int lane = threadIdx.x & 31;
    if (gw >= 2 * 6 * C_) return;
    int s = gw / (6 * C_), o = gw % (6 * C_);
    const float* Wp = (s ? Wtxt : Wimg) + (size_t)o * C_;
    float a0 = 0.f, a1 = 0.f;
    for (int c = lane; c < C_; c += 32) {
        float wv = Wp[c];
        a0 += wv * scond[c];
        a1 += wv * scond[C_ + c];
    }
    #pragma unroll
    for (int off = 16; off; off >>= 1) {
        a0 += __shfl_down_sync(0xffffffffu, a0, off);
        a1 += __shfl_down_sync(0xffffffffu, a1, off);
    }
    if (lane == 0) {
        float bb = (s ? btxt : bimg)[o];
        modout[(s * B_ + 0) * 6 * C_ + o] = a0 + bb;
        modout[(s * B_ + 1) * 6 * C_ + o] = a1 + bb;
    }
}

__global__ void __launch_bounds__(128)
buildx_k(const float* __restrict__ img, const float* __restrict__ txt,
         const float* __restrict__ rmswi, const float* __restrict__ rmswt,
         const float* __restrict__ mod, float* __restrict__ x) {
    int b = blockIdx.y;
    int l = blockIdx.x * 128 + threadIdx.x;
    const float* src; const float* rw; int Ls, li, s;
    if (l < LI_) { src = img; Ls = LI_; li = l;       s = 0; rw = rmswi; }
    else         { src = txt; Ls = LT_; li = l - LI_; s = 1; rw = rmswt; }
    const float* sp = src + (size_t)b * C_ * Ls + li;
    float ss = 0.f;
    #pragma unroll 8
    for (int c = 0; c < C_; c++) { float v = sp[(size_t)c * Ls]; ss += v * v; }
    float inv = rsqrtf(ss * (1.f / C_) + 1e-6f);
    const float* mb = mod + (s * B_ + b) * 6 * C_;
    float* xp = x + (size_t)b * C_ * L_ + l;
    #pragma unroll 8
    for (int c = 0; c < C_; c++) {
        float v = sp[(size_t)c * Ls];
        xp[(size_t)c * L_] = v * inv * rw[c] * (1.f + mb[C_ + c]) + mb[c];
    }
}

// ---------------- weight splits (A = [hi | lo] blocks) ----------------
// rkvg: A[4096][4096]: k<1024 Wd_hi | <2048 Ws_hi | <3072 Wd_lo | <4096 Ws_lo
__global__ void wsplit2_rkvg_k(const float* __restrict__ Wr, const float* __restrict__ Wk,
                               const float* __restrict__ Wv, const float* __restrict__ Wg,
                               const float* __restrict__ mur, const float* __restrict__ muk,
                               const float* __restrict__ muv, const float* __restrict__ mug,
                               __half* __restrict__ A) {
    size_t idx = (size_t)blockIdx.x * 256 + threadIdx.x;
    if (idx >= (size_t)4096 * 1024) return;
    int m = (int)(idx >> 10), c = (int)(idx & 1023);
    int p = m >> 10, mr = m & 1023;
    const float* W = (p == 0) ? Wr : (p == 1) ? Wk : (p == 2) ? Wv : Wg;
    const float* mu = (p == 0) ? mur : (p == 1) ? muk : (p == 2) ? muv : mug;
    float mm = mu[c];
    float wv = W[(size_t)mr * C_ + c];
    float wd = wv * (1.f - mm), ws = wv * mm;
    __half dh, dl, sh, sl;
    split_f16(wd, dh, dl); split_f16(ws, sh, sl);
    __half* o = A + (size_t)m * 4096 + c;
    o[0] = dh; o[1024] = sh; o[2048] = dl; o[3072] = sl;
}

// plain: W (M,K) -> A (M,2K): [hi | lo]
__global__ void wsplit2_plain_k(const float* __restrict__ W, __half* __restrict__ A,
                                int M, int K) {
    size_t idx = (size_t)blockIdx.x * 256 + threadIdx.x;
    if (idx >= (size_t)M * K) return;
    int m = (int)(idx / K), k = (int)(idx % K);
    __half hi, lo; split_f16(W[idx], hi, lo);
    __half* o = A + (size_t)m * 2 * K + k;
    o[0] = hi; o[K] = lo;
}

// ---------------- activation preps ----------------
// single-slot transpose: (B,CR,LL) fp32 -> (B,LL,CR) fp16
__global__ void __launch_bounds__(256)
asplit1_k(const float* __restrict__ in, __half* __restrict__ out, int CR, int LL) {
    __shared__ float tile[32][33];
    int b = blockIdx.z, c0 = blockIdx.y * 32, l0 = blockIdx.x * 32;
    int tx = threadIdx.x & 31, wy = threadIdx.x >> 5;
    const float* ip = in + ((size_t)b * CR + c0) * LL + l0;
    #pragma unroll
    for (int i = 0; i < 4; i++) { int c = wy + i * 8; tile[c][tx] = ip[(size_t)c * LL + tx]; }
    __syncthreads();
    #pragma unroll
    for (int i = 0; i < 4; i++) {
        int l = wy + i * 8;
        out[((size_t)b * LL + l0 + l) * CR + (c0 + tx)] = __float2half(tile[tx][l]);
    }
}

// x (B,C,L) -> Bx (B,L,2048): slot0 x_l, slot1 x_{l-1}
__global__ void __launch_bounds__(256)
asplit_shift_k(const float* __restrict__ x, __half* __restrict__ out) {
    __shared__ float tile[32][33];
    int b = blockIdx.z, c0 = blockIdx.y * 32, l0 = blockIdx.x * 32;
    int tx = threadIdx.x & 31, wy = threadIdx.x >> 5;
    const float* ip = x + ((size_t)b * C_ + c0) * L_ + l0;
    #pragma unroll
    for (int i = 0; i < 4; i++) { int c = wy + i * 8; tile[c][tx] = ip[(size_t)c * L_ + tx]; }
    __syncthreads();
    #pragma unroll
    for (int i = 0; i < 4; i++) {
        int l = l0 + wy + i * 8;
        __half hv = __float2half(tile[tx][wy + i * 8]);
        out[((size_t)b * L_ + l) * 2048 + (c0 + tx)] = hv;
        if (l + 1 < L_)
            out[((size_t)b * L_ + l + 1) * 2048 + 1024 + (c0 + tx)] = hv;
        if (l == 0)
            out[((size_t)b * L_) * 2048 + 1024 + (c0 + tx)] = __float2half(0.f);
    }
}

// ---------------- mma.sync GEMM ----------------
// K2 = 2*Kb (A [hi|lo]); B loaded with k mod Kb.
// MODE 0: plain fp32 (B,M,L).   MODE 1: rkvg -> r/k/v (B,H,L,N) fp32 + gate (B,L,C) fp32.
// MODE 2: gelu -> fp16 (B,L,M). MODE 3: resid + gate -> fp32 (B,M,L).
constexpr int STG = 18432;            // 128 rows * 144B
constexpr int GSMEM = 4 * STG;        // A0 A1 B0 B1

template <int MODE>
__global__ void __launch_bounds__(256, 2)
gemm_mma(const __half* __restrict__ A, const __half* __restrict__ Bm,
         float* __restrict__ Y, __half* __restrict__ Yh,
         float* __restrict__ ro, float* __restrict__ ko, float* __restrict__ vo,
         float* __restrict__ go,
         const float* __restrict__ resid, const float* __restrict__ gmod,
         int M, int K2, int Kb, int Llen) {
    extern __shared__ __align__(16) char dsmem[];
    uint32_t sb = smem_u32(dsmem);
    int tid = threadIdx.x, lane = tid & 31, wid = tid >> 5;
    int wm = wid >> 2, wn = wid & 3;
    int b = blockIdx.z, l0 = blockIdx.x * 128, m0 = blockIdx.y * 128;
    const int NT = K2 >> 6;

    float acc[4][4][4] = {};
    const __half* Ag = A + (size_t)m0 * K2;
    const __half* Bg = Bm + ((size_t)b * Llen + l0) * Kb;

    int r_ld = tid >> 1, seg = tid & 1;
    uint32_t soff = (uint32_t)(r_ld * 144 + seg * 64);
    const __half* Agr = Ag + (size_t)r_ld * K2 + seg * 32;
    const __half* Bgr = Bg + (size_t)r_ld * Kb + seg * 32;

    // prologue: tile 0
    #pragma unroll
    for (int j = 0; j < 4; j++) {
        cp16(sb + soff + j * 16,             Agr + j * 8);
        cp16(sb + 2 * STG + soff + j * 16,   Bgr + j * 8);
    }
    asm volatile("cp.async.commit_group;");

    for (int it = 0; it < NT; it++) {
        int q = it & 1;
        if (it + 1 < NT) {
            int qq = q ^ 1;
            int ka = (it + 1) * 64;
            int kb = ka >= Kb ? ka - Kb : ka;
            #pragma unroll
            for (int j = 0; j < 4; j++) {
                cp16(sb + qq * STG + soff + j * 16,           Agr + ka + j * 8);
                cp16(sb + 2 * STG + qq * STG + soff + j * 16, Bgr + kb + j * 8);
            }
            asm volatile("cp.async.commit_group;");
            asm volatile("cp.async.wait_group 1;");
        } else {
            asm volatile("cp.async.wait_group 0;");
        }
        __syncthreads();

        uint32_t baseA = sb + q * STG, baseB = sb + 2 * STG + q * STG;
        #pragma unroll
        for (int kk = 0; kk < 4; kk++) {
            uint32_t a[4][4], bq[2][4];
            #pragma unroll
            for (int ma = 0; ma < 4; ma++)
                ldsm4(a[ma], baseA + (wm * 64 + ma * 16 + (lane & 15)) * 144
                              + kk * 32 + (lane >> 4) * 16);
            #pragma unroll
            for (int nb = 0; nb < 2; nb++)
                ldsm4(bq[nb], baseB + (wn * 32 + nb * 16 + (lane & 7) + ((lane >> 4) & 1) * 8) * 144
                               + kk * 32 + ((lane >> 3) & 1) * 16);
            #pragma unroll
            for (int ma = 0; ma < 4; ma++)
                #pragma unroll
                for (int na = 0; na < 4; na++)
                    mma16816(acc[ma][na], a[ma], &bq[na >> 1][(na & 1) * 2]);
        }
        __syncthreads();
    }

    if (MODE == 0 || MODE == 3) {
        #pragma unroll
        for (int ma = 0; ma < 4; ma++) {
            #pragma unroll
            for (int hf = 0; hf < 2; hf++) {
                int m = m0 + wm * 64 + ma * 16 + (lane >> 2) + hf * 8;
                size_t ybase = ((size_t)b * M + m) * Llen;
                float gm = 0.f;
                if (MODE == 3) gm = gmod[b * 6 * C_ + m];
                #pragma unroll
                for (int na = 0; na < 4; na++) {
                    int col = l0 + wn * 32 + na * 8 + 2 * (lane & 3);
                    float v0 = acc[ma][na][hf * 2], v1 = acc[ma][na][hf * 2 + 1];
                    if (MODE == 3) {
                        float2 rr = *(const float2*)(resid + ybase + col);
                        v0 = rr.x + gm * v0;
                        v1 = rr.y + gm * v1;
                    }
                    *(float2*)(Y + ybase + col) = make_float2(v0, v1);
                }
            }
        }
    } else if (MODE == 1) {
        // smem transpose to [l][m] fp32, stride 132
        float* st = (float*)dsmem;
        int part = m0 >> 10;          // 0 r, 1 k, 2 v, 3 gate
        int c0 = m0 & 1023;
        #pragma unroll
        for (int ma = 0; ma < 4; ma++)
            #pragma unroll
            for (int na = 0; na < 4; na++)
                #pragma unroll
                for (int e = 0; e < 4; e++) {
                    int hf = e >> 1, j = e & 1;
                    int m = wm * 64 + ma * 16 + (lane >> 2) + hf * 8;
                    int l = wn * 32 + na * 8 + 2 * (lane & 3) + j;
                    float v = acc[ma][na][hf * 2 + j];
                    if (part == 3) v = v / (1.f + expf(-v));
                    st[l * 132 + m] = v;
                }
        __syncthreads();
        int l = tid >> 1, sg = tid & 1;
        const float* sp = st + l * 132 + sg * 64;
        if (part < 3) {
            float* outb = (part == 0) ? ro : (part == 1) ? ko : vo;
            int c = c0 + sg * 64;
            float* op = outb + ((size_t)(b * H_ + (c >> 6)) * L_ + l0 + l) * 64;
            #pragma unroll
            for (int j = 0; j < 64; j += 4)
                *(float4*)(op + j) = *(const float4*)(sp + j);
        } else {
            float* op = go + ((size_t)b * L_ + l0 + l) * C_ + c0 + sg * 64;
            #pragma unroll
            for (int j = 0; j < 64; j += 4)
                *(float4*)(op + j) = *(const float4*)(sp + j);
        }
    } else { // MODE 2: gelu, fp16 transpose out (B, L, M)
        __half* st = (__half*)dsmem;  // stride 136
        #pragma unroll
        for (int ma = 0; ma < 4; ma++)
            #pragma unroll
            for (int na = 0; na < 4; na++)
                #pragma unroll
                for (int e = 0; e < 4; e++) {
                    int hf = e >> 1, j = e & 1;
                    int m = wm * 64 + ma * 16 + (lane >> 2) + hf * 8;
                    int l = wn * 32 + na * 8 + 2 * (lane & 3) + j;
                    float v = acc[ma][na][hf * 2 + j];
                    float t = 0.7978845608f * (v + 0.044715f * v * v * v);
                    v = 0.5f * v * (1.f + tanhf(t));
                    st[l * 136 + m] = __float2half(v);
                }
        __syncthreads();
        int l = tid >> 1, sg = tid & 1;
        const uint4* sp = (const uint4*)(st + l * 136 + sg * 64);
        uint4* op = (uint4*)(Yh + ((size_t)b * Llen + l0 + l) * M + m0 + sg * 64);
        #pragma unroll
        for (int j = 0; j < 8; j++) op[j] = sp[j];
    }
}

// ---------------- RWKV scan ----------------
__global__ void __launch_bounds__(256)
scan_k(const float* __restrict__ rr, const float* __restrict__ kk,
       const float* __restrict__ vv, const float* __restrict__ td,
       const float* __restrict__ tf, float* __restrict__ yy) {
    int bh = blockIdx.x >> 1;
    int mh = blockIdx.x & 1;
    int tid = threadIdx.x;
    int m = tid & 31, ng = tid >> 5;
    int h = bh & (H_ - 1);
    size_t base = (size_t)bh * L_ * N_;

    __shared__ float sr[64], sk[64], sv[64], su[64];
    __shared__ float ps[256];
    __shared__ float sruk;

    if (tid < 64) su[tid] = tf[h * N_ + tid];
    float w[8], S[8];
    #pragma unroll
    for (int i = 0; i < 8; i++) {
        int n = ng * 8 + i;
        w[i] = expf(-expf(td[h * N_ + n]));
        S[i] = 0.f;
    }
    __syncthreads();

    int gm = mh * 32 + m;
    for (int l = 0; l < L_; l++) {
        size_t off = base + (size_t)l * N_;
        if (tid < 64)        sr[tid]       = rr[off + tid];
        else if (tid < 128)  sk[tid - 64]  = kk[off + tid - 64];
        else if (tid < 192)  sv[tid - 128] = vv[off + tid - 128];
        __syncthreads();

        if (tid < 32) {
            float p = sr[tid] * su[tid] * sk[tid] + sr[tid + 32] * su[tid + 32] * sk[tid + 32];
            #pragma unroll
            for (int o = 16; o; o >>= 1) p += __shfl_down_sync(0xffffffffu, p, o);
            if (tid == 0) sruk = p;
        }

        float vm = sv[gm];
        float4 r0 = *(const float4*)&sr[ng * 8];
        float4 r1 = *(const float4*)&sr[ng * 8 + 4];
        float4 k0 = *(const float4*)&sk[ng * 8];
        float4 k1 = *(const float4*)&sk[ng * 8 + 4];
        float rv[8] = {r0.x, r0.y, r0.z, r0.w, r1.x, r1.y, r1.z, r1.w};
        float kv[8] = {k0.x, k0.y, k0.z, k0.w, k1.x, k1.y, k1.z, k1.w};

        float partial = 0.f;
        #pragma unroll
        for (int i = 0; i < 8; i++) {
            partial += rv[i] * S[i];
            S[i] = w[i] * S[i] + kv[i] * vm;
        }
        ps[tid] = partial;
        __syncthreads();

        if (tid < 32) {
            float y = sruk * vm;
            #pragma unroll
            for (int j = 0; j < 8; j++) y += ps[m + 32 * j];
            yy[off + gm] = y;
        }
        __syncthreads();
    }
}

// ---------------- groupnorm * ln_x * gate -> fp16 (B,L,C) ----------------
__global__ void __launch_bounds__(256)
gnorm_k(const float* __restrict__ yy, const float* __restrict__ gate,
        const float* __restrict__ lnw, const float* __restrict__ lnb,
        __half* __restrict__ z) {
    int b = blockIdx.z, h = blockIdx.y, l0 = blockIdx.x * 64;
    __shared__ float tile[64][65];
    __shared__ float rs1[4][64], rs2[4][64];
    __shared__ float smean[64], sinv[64];
    int tid = threadIdx.x;
    size_t ybase = ((size_t)(b * H_ + h) * L_ + l0) * N_;

    #pragma unroll
    for (int i = 0; i < 16; i++) {
        int id = tid + i * 256;
        int row = id >> 6, col = id & 63;
        tile[col][row] = yy[ybase + (size_t)row * N_ + col];
    }
    __syncthreads();
    {
        int l = tid & 63, part = tid >> 6;
        float s1 = 0.f, s2 = 0.f;
        #pragma unroll
        for (int i = 0; i < 16; i++) {
            float v = tile[part * 16 + i][l];
            s1 += v; s2 += v * v;
        }
        rs1[part][l] = s1; rs2[part][l] = s2;
    }
    __syncthreads();
    if (tid < 64) {
        float s1 = rs1[0][tid] + rs1[1][tid] + rs1[2][tid] + rs1[3][tid];
        float s2 = rs2[0][tid] + rs2[1][tid] + rs2[2][tid] + rs2[3][tid];
        float mean = s1 * (1.f / 64);
        float var = s2 * (1.f / 64) - mean * mean;
        smean[tid] = mean;
        sinv[tid] = rsqrtf(var + 1e-5f);
    }
    __syncthreads();

    int n = tid >> 2, lq = tid & 3;
    int c = h * 64 + n;
    float lw = lnw[c], lb = lnb[c];
    #pragma unroll
    for (int q = 0; q < 16; q++) {
        int l = lq * 16 + q;
        size_t rofs = ((size_t)b * L_ + l0 + l) * C_ + c;
        float v = ((tile[n][l] - smean[l]) * sinv[l] * lw + lb) * gate[rofs];
        z[rofs] = __float2half(v);
    }
}

// ---------------- residual + rms (block per 128 l) ----------------
__global__ void __launch_bounds__(128)
resid_rms_k(const float* __restrict__ img, const float* __restrict__ txt,
            const float* __restrict__ attn, const float* __restrict__ mod,
            const float* __restrict__ w2i, const float* __restrict__ w2t,
            float* __restrict__ img1, float* __restrict__ txt1,
            float* __restrict__ himg, float* __restrict__ htxt) {
    int b = blockIdx.y;
    int l = blockIdx.x * 128 + threadIdx.x;
    int s, li, Ls;
    const float* src; float* d1; float* dh; const float* rw;
    if (l < LI_) { s = 0; li = l;       Ls = LI_; src = img; d1 = img1; dh = himg; rw = w2i; }
    else         { s = 1; li = l - LI_; Ls = LT_; src = txt; d1 = txt1; dh = htxt; rw = w2t; }
    const float* mb = mod + (s * B_ + b) * 6 * C_;
    const float* ap = attn + (size_t)b * C_ * L_ + l;
    const float* sp = src + (size_t)b * C_ * Ls + li;
    float* p1 = d1 + (size_t)b * C_ * Ls + li;
    float* ph = dh + (size_t)b * C_ * Ls + li;
    float ss = 0.f;
    #pragma unroll 4
    for (int c = 0; c < C_; c++) {
        float v = sp[(size_t)c * Ls] + mb[2 * C_ + c] * ap[(size_t)c * L_];
        p1[(size_t)c * Ls] = v;
        ss += v * v;
    }
    float inv = rsqrtf(ss * (1.f / C_) + 1e-6f);
    #pragma unroll 4
    for (int c = 0; c < C_; c++) {
        float v = p1[(size_t)c * Ls];
        ph[(size_t)c * Ls] = v * inv * rw[c] * (1.f + mb[4 * C_ + c]) + mb[3 * C_ + c];
    }
}

// ---------------- host ----------------
static float* symaddr(const void* s) {
    void* p = nullptr;
    cudaGetSymbolAddress(&p, s);
    return (float*)p;
}
static __half* symaddrh(const void* s) {
    void* p = nullptr;
    cudaGetSymbolAddress(&p, s);
    return (__half*)p;
}

extern "C" void kernel_launch(void* const* d_in, const int* in_sizes, int n_in,
                              void* d_out, int out_size) {
    const float* img   = (const float*)d_in[0];
    const float* txt   = (const float*)d_in[1];
    const float* cond  = (const float*)d_in[2];
    const float* Wmi   = (const float*)d_in[3];
    const float* bmi   = (const float*)d_in[4];
    const float* Wmt   = (const float*)d_in[5];
    const float* bmt   = (const float*)d_in[6];
    const float* rmsi  = (const float*)d_in[7];
    const float* rmst  = (const float*)d_in[8];
    const float* rmsi2 = (const float*)d_in[9];
    const float* rmst2 = (const float*)d_in[10];
    const float* mur   = (const float*)d_in[11];
    const float* muk   = (const float*)d_in[12];
    const float* muv   = (const float*)d_in[13];
    const float* mug   = (const float*)d_in[14];
    const float* Wr    = (const float*)d_in[15];
    const float* Wk    = (const float*)d_in[16];
    const float* Wv    = (const float*)d_in[17];
    const float* Wg    = (const float*)d_in[18];
    const float* Wo    = (const float*)d_in[19];
    const float* td    = (const float*)d_in[20];
    const float* tf    = (const float*)d_in[21];
    const float* lnw   = (const float*)d_in[22];
    const float* lnb   = (const float*)d_in[23];
    const float* fi1   = (const float*)d_in[24];
    const float* fi2   = (const float*)d_in[25];
    const float* ft1   = (const float*)d_in[26];
    const float* ft2   = (const float*)d_in[27];

    float* p_scond = symaddr(g_scond);
    float* p_mod   = symaddr(g_mod);
    float* p_x     = symaddr(g_x);
    float* p_gate  = symaddr(g_gate);
    float* p_r     = symaddr(g_r);
    float* p_k     = symaddr(g_k);
    float* p_v     = symaddr(g_v);
    float* p_y     = symaddr(g_y);
    float* p_attn  = symaddr(g_attn);
    float* p_img1  = symaddr(g_img1);
    float* p_txt1  = symaddr(g_txt1);
    float* p_himg  = symaddr(g_himg);
    float* p_htxt  = symaddr(g_htxt);

    __half* pArkvg = symaddrh(g_Arkvg);
    __half* pAwo   = symaddrh(g_Awo);
    __half* pAfi1  = symaddrh(g_Afi1);
    __half* pAfi2  = symaddrh(g_Afi2);
    __half* pAft1  = symaddrh(g_Aft1);
    __half* pAft2  = symaddrh(g_Aft2);
    __half* pBx    = symaddrh(g_Bx);
    __half* pBz    = symaddrh(g_Bz);
    __half* pBhi   = symaddrh(g_Bhi);
    __half* pBht   = symaddrh(g_Bht);
    __half* pBmi   = symaddrh(g_Bmi);
    __half* pBmt   = symaddrh(g_Bmt);

    float* out_img = (float*)d_out;
    float* out_txt = out_img + IMGSZ;

    cudaFuncSetAttribute(gemm_mma<0>, cudaFuncAttributeMaxDynamicSharedMemorySize, GSMEM);
    cudaFuncSetAttribute(gemm_mma<1>, cudaFuncAttributeMaxDynamicSharedMemorySize, GSMEM);
    cudaFuncSetAttribute(gemm_mma<2>, cudaFuncAttributeMaxDynamicSharedMemorySize, GSMEM);
    cudaFuncSetAttribute(gemm_mma<3>, cudaFuncAttributeMaxDynamicSharedMemorySize, GSMEM);

    // 1) modulation
    silu_cond_k<<<(B_ * C_ + 255) / 256, 256>>>(cond, p_scond);
    mod_k<<<(2 * 6 * C_) / 8, 256>>>(Wmi, bmi, Wmt, bmt, p_scond, p_mod);

    // 2) weight splits
    wsplit2_rkvg_k<<<(4096 * 1024) / 256, 256>>>(Wr, Wk, Wv, Wg, mur, muk, muv, mug, pArkvg);
    wsplit2_plain_k<<<(1024 * 1024) / 256, 256>>>(Wo,  pAwo,  1024, 1024);
    wsplit2_plain_k<<<(2048 * 1024) / 256, 256>>>(fi1, pAfi1, 2048, 1024);
    wsplit2_plain_k<<<(1024 * 2048) / 256, 256>>>(fi2, pAfi2, 1024, 2048);
    wsplit2_plain_k<<<(2048 * 1024) / 256, 256>>>(ft1, pAft1, 2048, 1024);
    wsplit2_plain_k<<<(1024 * 2048) / 256, 256>>>(ft2, pAft2, 1024, 2048);

    // 3) x, shift-pack
    buildx_k<<<dim3(L_ / 128, B_), 128>>>(img, txt, rmsi, rmst, p_mod, p_x);
    asplit_shift_k<<<dim3(L_ / 32, C_ / 32, B_), 256>>>(p_x, pBx);

    // 4) fused rkvg GEMM: r/k/v -> (B,H,L,N), gate -> (B,L,C)
    gemm_mma<1><<<dim3(L_ / 128, 4096 / 128, B_), 256, GSMEM>>>(
        pArkvg, pBx, nullptr, nullptr, p_r, p_k, p_v, p_gate,
        nullptr, nullptr, 4096, 4096, 2048, L_);

    // 5) scan
    scan_k<<<B_ * H_ * 2, 256>>>(p_r, p_k, p_v, td, tf, p_y);

    // 6) groupnorm * gate -> fp16 (B,L,C)
    gnorm_k<<<dim3(L_ / 64, H_, B_), 256>>>(p_y, p_gate, lnw, lnb, pBz);

    // 7) Wo GEMM -> attn (B,C,L)
    gemm_mma<0><<<dim3(L_ / 128, C_ / 128, B_), 256, GSMEM>>>(
        pAwo, pBz, p_attn, nullptr, nullptr, nullptr, nullptr, nullptr,
        nullptr, nullptr, C_, 2048, 1024, L_);

    // 8) residual + rms
    resid_rms_k<<<dim3(L_ / 128, B_), 128>>>(img, txt, p_attn, p_mod, rmsi2, rmst2,
                                             p_img1, p_txt1, p_himg, p_htxt);

    // 9) FFN img
    asplit1_k<<<dim3(LI_ / 32, C_ / 32, B_), 256>>>(p_himg, pBhi, C_, LI_);
    gemm_mma<2><<<dim3(LI_ / 128, HID_ / 128, B_), 256, GSMEM>>>(
        pAfi1, pBhi, nullptr, pBmi, nullptr, nullptr, nullptr, nullptr,
        nullptr, nullptr, HID_, 2048, 1024, LI_);
    gemm_mma<3><<<dim3(LI_ / 128, C_ / 128, B_), 256, GSMEM>>>(
        pAfi2, pBmi, out_img, nullptr, nullptr, nullptr, nullptr, nullptr,
        p_img1, p_mod + 5 * C_, C_, 4096, 2048, LI_);

    // 10) FFN txt
    asplit1_k<<<dim3(LT_ / 32, C_ / 32, B_), 256>>>(p_htxt, pBht, C_, LT_);
    gemm_mma<2><<<dim3(LT_ / 128, HID_ / 128, B_), 256, GSMEM>>>(
        pAft1, pBht, nullptr, pBmt, nullptr, nullptr, nullptr, nullptr,
        nullptr, nullptr, HID_, 2048, 1024, LT_);
    gemm_mma<3><<<dim3(LT_ / 128, C_ / 128, B_), 256, GSMEM>>>(
        pAft2, pBmt, out_txt, nullptr, nullptr, nullptr, nullptr, nullptr,
        p_txt1, p_mod + B_ * 6 * C_ + 5 * C_, C_, 4096, 2048, LT_);
}

// round 8
// speedup vs baseline: 2.4023x; 1.5288x over previous
#include <cuda_runtime.h>
#include <cuda_fp16.h>
#include <math.h>
#include <stdint.h>

constexpr int B_  = 2;
constexpr int C_  = 1024;
constexpr int H_  = 16;
constexpr int N_  = 64;
constexpr int LI_ = 4096;
constexpr int LT_ = 512;
constexpr int L_  = LI_ + LT_;   // 4608
constexpr int HID_ = 2048;

constexpr size_t XSZ   = (size_t)B_ * C_ * L_;
constexpr size_t IMGSZ = (size_t)B_ * C_ * LI_;
constexpr size_t TXTSZ = (size_t)B_ * C_ * LT_;

// ---------------- static scratch ----------------
__device__ float g_scond[B_ * C_];
__device__ float g_mod[2 * B_ * 6 * C_];
__device__ float g_x[XSZ];
__device__ float g_gate[XSZ];                        // silu(g) in (B,L,C)
__device__ float g_r[XSZ];                           // (B,H,L,N)
__device__ float g_k[XSZ];
__device__ float g_v[XSZ];
__device__ float g_y[XSZ];
__device__ float g_attn[XSZ];                        // (B,C,L)
__device__ float g_img1[IMGSZ];
__device__ float g_txt1[TXTSZ];
__device__ float g_himg[IMGSZ];
__device__ float g_htxt[TXTSZ];

// fp16 GEMM operands (A = [hi | lo] 2K blocks; B = single fp16)
__device__ __half g_Arkvg[(size_t)4096 * 4096];
__device__ __half g_Awo [(size_t)1024 * 2048];
__device__ __half g_Afi1[(size_t)2048 * 2048];
__device__ __half g_Afi2[(size_t)1024 * 4096];
__device__ __half g_Aft1[(size_t)2048 * 2048];
__device__ __half g_Aft2[(size_t)1024 * 4096];
__device__ __half g_Bx [(size_t)B_ * L_  * 2048];    // [x_l | x_{l-1}]
__device__ __half g_Bz [(size_t)B_ * L_  * 1024];
__device__ __half g_Bhi[(size_t)B_ * LI_ * 1024];
__device__ __half g_Bht[(size_t)B_ * LT_ * 1024];
__device__ __half g_Bmi[(size_t)B_ * LI_ * 2048];    // ffn1 img out (fp16, direct)
__device__ __half g_Bmt[(size_t)B_ * LT_ * 2048];

// ---------------- helpers ----------------
__device__ __forceinline__ uint32_t smem_u32(const void* p) {
    uint32_t r;
    asm("{ .reg .u64 t; cvta.to.shared.u64 t, %1; cvt.u32.u64 %0, t; }" : "=r"(r) : "l"(p));
    return r;
}
__device__ __forceinline__ void cp16(uint32_t s, const void* g) {
    asm volatile("cp.async.cg.shared.global [%0], [%1], 16;" :: "r"(s), "l"(g));
}
__device__ __forceinline__ void ldsm4(uint32_t* r, uint32_t addr) {
    asm volatile("ldmatrix.sync.aligned.m8n8.x4.shared.b16 {%0,%1,%2,%3},[%4];"
                 : "=r"(r[0]), "=r"(r[1]), "=r"(r[2]), "=r"(r[3]) : "r"(addr));
}
__device__ __forceinline__ void mma16816(float* d, const uint32_t* a, const uint32_t* b) {
    asm volatile("mma.sync.aligned.m16n8k16.row.col.f32.f16.f16.f32 "
                 "{%0,%1,%2,%3},{%4,%5,%6,%7},{%8,%9},{%0,%1,%2,%3};"
                 : "+f"(d[0]), "+f"(d[1]), "+f"(d[2]), "+f"(d[3])
                 : "r"(a[0]), "r"(a[1]), "r"(a[2]), "r"(a[3]), "r"(b[0]), "r"(b[1]));
}
__device__ __forceinline__ void split_f16(float v, __half& hi, __half& lo) {
    hi = __float2half(v);
    lo = __float2half(v - __half2float(hi));
}

// ---------------- small elementwise ----------------
__global__ void silu_cond_k(const float* __restrict__ cond, float* __restrict__ out) {
    int i = blockIdx.x * blockDim.x + threadIdx.x;
    if (i < B_ * C_) { float v = cond[i]; out[i] = v / (1.f + expf(-v)); }
}

__global__ void mod_k(const float* __restrict__ Wimg, const float* __restrict__ bimg,
                      const float* __restrict__ Wtxt, const float* __restrict__ btxt,
                      const float* __restrict__ scond, float* __restrict__ modout) {
    int gw = (blockIdx.x * blockDim.x + threadIdx.x) >> 5;
    int lane = threadIdx.x & 31;
    if (gw >= 2 * 6 * C_) return;
    int s = gw / (6 * C_), o = gw % (6 * C_);
    const float* Wp = (s ? Wtxt : Wimg) + (size_t)o * C_;
    float a0 = 0.f, a1 = 0.f;
    for (int c = lane; c < C_; c += 32) {
        float wv = Wp[c];
        a0 += wv * scond[c];
        a1 += wv * scond[C_ + c];
    }
    #pragma unroll
    for (int off = 16; off; off >>= 1) {
        a0 += __shfl_down_sync(0xffffffffu, a0, off);
        a1 += __shfl_down_sync(0xffffffffu, a1, off);
    }
    if (lane == 0) {
        float bb = (s ? btxt : bimg)[o];
        modout[(s * B_ + 0) * 6 * C_ + o] = a0 + bb;
        modout[(s * B_ + 1) * 6 * C_ + o] = a1 + bb;
    }
}

__global__ void __launch_bounds__(128)
buildx_k(const float* __restrict__ img, const float* __restrict__ txt,
         const float* __restrict__ rmswi, const float* __restrict__ rmswt,
         const float* __restrict__ mod, float* __restrict__ x) {
    int b = blockIdx.y;
    int l = blockIdx.x * 128 + threadIdx.x;
    const float* src; const float* rw; int Ls, li, s;
    if (l < LI_) { src = img; Ls = LI_; li = l;       s = 0; rw = rmswi; }
    else         { src = txt; Ls = LT_; li = l - LI_; s = 1; rw = rmswt; }
    const float* sp = src + (size_t)b * C_ * Ls + li;
    float ss = 0.f;
    #pragma unroll 8
    for (int c = 0; c < C_; c++) { float v = sp[(size_t)c * Ls]; ss += v * v; }
    float inv = rsqrtf(ss * (1.f / C_) + 1e-6f);
    const float* mb = mod + (s * B_ + b) * 6 * C_;
    float* xp = x + (size_t)b * C_ * L_ + l;
    #pragma unroll 8
    for (int c = 0; c < C_; c++) {
        float v = sp[(size_t)c * Ls];
        xp[(size_t)c * L_] = v * inv * rw[c] * (1.f + mb[C_ + c]) + mb[c];
    }
}

// ---------------- weight splits ----------------
__global__ void wsplit2_rkvg_k(const float* __restrict__ Wr, const float* __restrict__ Wk,
                               const float* __restrict__ Wv, const float* __restrict__ Wg,
                               const float* __restrict__ mur, const float* __restrict__ muk,
                               const float* __restrict__ muv, const float* __restrict__ mug,
                               __half* __restrict__ A) {
    size_t idx = (size_t)blockIdx.x * 256 + threadIdx.x;
    if (idx >= (size_t)4096 * 1024) return;
    int m = (int)(idx >> 10), c = (int)(idx & 1023);
    int p = m >> 10, mr = m & 1023;
    const float* W = (p == 0) ? Wr : (p == 1) ? Wk : (p == 2) ? Wv : Wg;
    const float* mu = (p == 0) ? mur : (p == 1) ? muk : (p == 2) ? muv : mug;
    float mm = mu[c];
    float wv = W[(size_t)mr * C_ + c];
    float wd = wv * (1.f - mm), ws = wv * mm;
    __half dh, dl, sh, sl;
    split_f16(wd, dh, dl); split_f16(ws, sh, sl);
    __half* o = A + (size_t)m * 4096 + c;
    o[0] = dh; o[1024] = sh; o[2048] = dl; o[3072] = sl;
}

__global__ void wsplit2_plain_k(const float* __restrict__ W, __half* __restrict__ A,
                                int M, int K) {
    size_t idx = (size_t)blockIdx.x * 256 + threadIdx.x;
    if (idx >= (size_t)M * K) return;
    int m = (int)(idx / K), k = (int)(idx % K);
    __half hi, lo; split_f16(W[idx], hi, lo);
    __half* o = A + (size_t)m * 2 * K + k;
    o[0] = hi; o[K] = lo;
}

// ---------------- activation preps ----------------
__global__ void __launch_bounds__(256)
asplit1_k(const float* __restrict__ in, __half* __restrict__ out, int CR, int LL) {
    __shared__ float tile[32][33];
    int b = blockIdx.z, c0 = blockIdx.y * 32, l0 = blockIdx.x * 32;
    int tx = threadIdx.x & 31, wy = threadIdx.x >> 5;
    const float* ip = in + ((size_t)b * CR + c0) * LL + l0;
    #pragma unroll
    for (int i = 0; i < 4; i++) { int c = wy + i * 8; tile[c][tx] = ip[(size_t)c * LL + tx]; }
    __syncthreads();
    #pragma unroll
    for (int i = 0; i < 4; i++) {
        int l = wy + i * 8;
        out[((size_t)b * LL + l0 + l) * CR + (c0 + tx)] = __float2half(tile[tx][l]);
    }
}

__global__ void __launch_bounds__(256)
asplit_shift_k(const float* __restrict__ x, __half* __restrict__ out) {
    __shared__ float tile[32][33];
    int b = blockIdx.z, c0 = blockIdx.y * 32, l0 = blockIdx.x * 32;
    int tx = threadIdx.x & 31, wy = threadIdx.x >> 5;
    const float* ip = x + ((size_t)b * C_ + c0) * L_ + l0;
    #pragma unroll
    for (int i = 0; i < 4; i++) { int c = wy + i * 8; tile[c][tx] = ip[(size_t)c * L_ + tx]; }
    __syncthreads();
    #pragma unroll
    for (int i = 0; i < 4; i++) {
        int l = l0 + wy + i * 8;
        __half hv = __float2half(tile[tx][wy + i * 8]);
        out[((size_t)b * L_ + l) * 2048 + (c0 + tx)] = hv;
        if (l + 1 < L_)
            out[((size_t)b * L_ + l + 1) * 2048 + 1024 + (c0 + tx)] = hv;
        if (l == 0)
            out[((size_t)b * L_) * 2048 + 1024 + (c0 + tx)] = __float2half(0.f);
    }
}

// ---------------- mma.sync GEMM ----------------
constexpr int STG = 18432;            // 128 rows * 144B
constexpr int GSMEM = 4 * STG;

template <int MODE>
__global__ void __launch_bounds__(256, 2)
gemm_mma(const __half* __restrict__ A, const __half* __restrict__ Bm,
         float* __restrict__ Y, __half* __restrict__ Yh,
         float* __restrict__ ro, float* __restrict__ ko, float* __restrict__ vo,
         float* __restrict__ go,
         const float* __restrict__ resid, const float* __restrict__ gmod,
         int M, int K2, int Kb, int Llen) {
    extern __shared__ __align__(16) char dsmem[];
    uint32_t sb = smem_u32(dsmem);
    int tid = threadIdx.x, lane = tid & 31, wid = tid >> 5;
    int wm = wid >> 2, wn = wid & 3;
    int b = blockIdx.z, l0 = blockIdx.x * 128, m0 = blockIdx.y * 128;
    const int NT = K2 >> 6;

    float acc[4][4][4] = {};
    const __half* Ag = A + (size_t)m0 * K2;
    const __half* Bg = Bm + ((size_t)b * Llen + l0) * Kb;

    int r_ld = tid >> 1, seg = tid & 1;
    uint32_t soff = (uint32_t)(r_ld * 144 + seg * 64);
    const __half* Agr = Ag + (size_t)r_ld * K2 + seg * 32;
    const __half* Bgr = Bg + (size_t)r_ld * Kb + seg * 32;

    #pragma unroll
    for (int j = 0; j < 4; j++) {
        cp16(sb + soff + j * 16,             Agr + j * 8);
        cp16(sb + 2 * STG + soff + j * 16,   Bgr + j * 8);
    }
    asm volatile("cp.async.commit_group;");

    for (int it = 0; it < NT; it++) {
        int q = it & 1;
        if (it + 1 < NT) {
            int qq = q ^ 1;
            int ka = (it + 1) * 64;
            int kb = ka >= Kb ? ka - Kb : ka;
            #pragma unroll
            for (int j = 0; j < 4; j++) {
                cp16(sb + qq * STG + soff + j * 16,           Agr + ka + j * 8);
                cp16(sb + 2 * STG + qq * STG + soff + j * 16, Bgr + kb + j * 8);
            }
            asm volatile("cp.async.commit_group;");
            asm volatile("cp.async.wait_group 1;");
        } else {
            asm volatile("cp.async.wait_group 0;");
        }
        __syncthreads();

        uint32_t baseA = sb + q * STG, baseB = sb + 2 * STG + q * STG;
        #pragma unroll
        for (int kk = 0; kk < 4; kk++) {
            uint32_t a[4][4], bq[2][4];
            #pragma unroll
            for (int ma = 0; ma < 4; ma++)
                ldsm4(a[ma], baseA + (wm * 64 + ma * 16 + (lane & 15)) * 144
                              + kk * 32 + (lane >> 4) * 16);
            #pragma unroll
            for (int nb = 0; nb < 2; nb++)
                ldsm4(bq[nb], baseB + (wn * 32 + nb * 16 + (lane & 7) + ((lane >> 4) & 1) * 8) * 144
                               + kk * 32 + ((lane >> 3) & 1) * 16);
            #pragma unroll
            for (int ma = 0; ma < 4; ma++)
                #pragma unroll
                for (int na = 0; na < 4; na++)
                    mma16816(acc[ma][na], a[ma], &bq[na >> 1][(na & 1) * 2]);
        }
        __syncthreads();
    }

    if (MODE == 0 || MODE == 3) {
        #pragma unroll
        for (int ma = 0; ma < 4; ma++) {
            #pragma unroll
            for (int hf = 0; hf < 2; hf++) {
                int m = m0 + wm * 64 + ma * 16 + (lane >> 2) + hf * 8;
                size_t ybase = ((size_t)b * M + m) * Llen;
                float gm = 0.f;
                if (MODE == 3) gm = gmod[b * 6 * C_ + m];
                #pragma unroll
                for (int na = 0; na < 4; na++) {
                    int col = l0 + wn * 32 + na * 8 + 2 * (lane & 3);
                    float v0 = acc[ma][na][hf * 2], v1 = acc[ma][na][hf * 2 + 1];
                    if (MODE == 3) {
                        float2 rr = *(const float2*)(resid + ybase + col);
                        v0 = rr.x + gm * v0;
                        v1 = rr.y + gm * v1;
                    }
                    *(float2*)(Y + ybase + col) = make_float2(v0, v1);
                }
            }
        }
    } else if (MODE == 1) {
        float* st = (float*)dsmem;
        int part = m0 >> 10;
        int c0 = m0 & 1023;
        #pragma unroll
        for (int ma = 0; ma < 4; ma++)
            #pragma unroll
            for (int na = 0; na < 4; na++)
                #pragma unroll
                for (int e = 0; e < 4; e++) {
                    int hf = e >> 1, j = e & 1;
                    int m = wm * 64 + ma * 16 + (lane >> 2) + hf * 8;
                    int l = wn * 32 + na * 8 + 2 * (lane & 3) + j;
                    float v = acc[ma][na][hf * 2 + j];
                    if (part == 3) v = v / (1.f + expf(-v));
                    st[l * 132 + m] = v;
                }
        __syncthreads();
        int l = tid >> 1, sg = tid & 1;
        const float* sp = st + l * 132 + sg * 64;
        if (part < 3) {
            float* outb = (part == 0) ? ro : (part == 1) ? ko : vo;
            int c = c0 + sg * 64;
            float* op = outb + ((size_t)(b * H_ + (c >> 6)) * L_ + l0 + l) * 64;
            #pragma unroll
            for (int j = 0; j < 64; j += 4)
                *(float4*)(op + j) = *(const float4*)(sp + j);
        } else {
            float* op = go + ((size_t)b * L_ + l0 + l) * C_ + c0 + sg * 64;
            #pragma unroll
            for (int j = 0; j < 64; j += 4)
                *(float4*)(op + j) = *(const float4*)(sp + j);
        }
    } else { // MODE 2
        __half* st = (__half*)dsmem;
        #pragma unroll
        for (int ma = 0; ma < 4; ma++)
            #pragma unroll
            for (int na = 0; na < 4; na++)
                #pragma unroll
                for (int e = 0; e < 4; e++) {
                    int hf = e >> 1, j = e & 1;
                    int m = wm * 64 + ma * 16 + (lane >> 2) + hf * 8;
                    int l = wn * 32 + na * 8 + 2 * (lane & 3) + j;
                    float v = acc[ma][na][hf * 2 + j];
                    float t = 0.7978845608f * (v + 0.044715f * v * v * v);
                    v = 0.5f * v * (1.f + tanhf(t));
                    st[l * 136 + m] = __float2half(v);
                }
        __syncthreads();
        int l = tid >> 1, sg = tid & 1;
        const uint4* sp = (const uint4*)(st + l * 136 + sg * 64);
        uint4* op = (uint4*)(Yh + ((size_t)b * Llen + l0 + l) * M + m0 + sg * 64);
        #pragma unroll
        for (int j = 0; j < 8; j++) op[j] = sp[j];
    }
}

// ---------------- RWKV scan: chunked cp.async + shuffle reductions ----------------
// block per (b,h); 256 threads: m = tid>>2 (0..63), ns = tid&3 (16 n each)
constexpr int SCH = 16;               // steps per chunk; L_ % SCH == 0
__global__ void __launch_bounds__(256)
scan_k(const float* __restrict__ rr, const float* __restrict__ kk,
       const float* __restrict__ vv, const float* __restrict__ td,
       const float* __restrict__ tf, float* __restrict__ yy) {
    __shared__ __align__(16) float rs[2][SCH * 64];
    __shared__ __align__(16) float ks[2][SCH * 64];
    __shared__ __align__(16) float vs[2][SCH * 64];
    int bh = blockIdx.x;
    int h = bh & (H_ - 1);
    int tid = threadIdx.x;
    int m = tid >> 2, ns = tid & 3;
    size_t base = (size_t)bh * L_ * N_;

    float S[16], w[16], u[16];
    #pragma unroll
    for (int i = 0; i < 16; i++) {
        int n = ns * 16 + i;
        w[i] = expf(-expf(td[h * N_ + n]));
        u[i] = tf[h * N_ + n];
        S[i] = 0.f;
    }

    uint32_t sr = smem_u32(rs), sk = smem_u32(ks), sv = smem_u32(vs);
    const int NCH = L_ / SCH;
    uint32_t toff = (uint32_t)tid * 16;

    // prologue: chunk 0 into buf 0
    cp16(sr + toff, rr + base + tid * 4);
    cp16(sk + toff, kk + base + tid * 4);
    cp16(sv + toff, vv + base + tid * 4);
    asm volatile("cp.async.commit_group;");
    asm volatile("cp.async.wait_group 0;");
    __syncthreads();

    for (int ch = 0; ch < NCH; ch++) {
        int q = ch & 1;
        if (ch + 1 < NCH) {
            uint32_t dst = (uint32_t)((q ^ 1) * SCH * 64 * 4) + toff;
            size_t gof = base + (size_t)(ch + 1) * SCH * 64 + tid * 4;
            cp16(sr + dst, rr + gof);
            cp16(sk + dst, kk + gof);
            cp16(sv + dst, vv + gof);
            asm volatile("cp.async.commit_group;");
        }
        const float* rb = rs[q];
        const float* kb = ks[q];
        const float* vb = vs[q];
        size_t yof = base + (size_t)ch * SCH * 64 + m;
        #pragma unroll 4
        for (int s = 0; s < SCH; s++) {
            const float* rp = rb + s * 64 + ns * 16;
            const float* kp = kb + s * 64 + ns * 16;
            float vm = vb[s * 64 + m];
            float t = 0.f, qq = 0.f;
            #pragma unroll
            for (int i = 0; i < 16; i += 4) {
                float4 r4 = *(const float4*)(rp + i);
                float4 k4 = *(const float4*)(kp + i);
                float rv[4] = {r4.x, r4.y, r4.z, r4.w};
                float kv[4] = {k4.x, k4.y, k4.z, k4.w};
                #pragma unroll
                for (int j = 0; j < 4; j++) {
                    int i2 = i + j;
                    t += rv[j] * S[i2];
                    qq += rv[j] * u[i2] * kv[j];
                    S[i2] = w[i2] * S[i2] + kv[j] * vm;
                }
            }
            t  += __shfl_xor_sync(0xffffffffu, t, 1);
            t  += __shfl_xor_sync(0xffffffffu, t, 2);
            qq += __shfl_xor_sync(0xffffffffu, qq, 1);
            qq += __shfl_xor_sync(0xffffffffu, qq, 2);
            if (ns == 0) yy[yof + (size_t)s * 64] = t + qq * vm;
        }
        if (ch + 1 < NCH) asm volatile("cp.async.wait_group 0;");
        __syncthreads();
    }
}

// ---------------- groupnorm * ln_x * gate -> fp16 (B,L,C) ----------------
__global__ void __launch_bounds__(256)
gnorm_k(const float* __restrict__ yy, const float* __restrict__ gate,
        const float* __restrict__ lnw, const float* __restrict__ lnb,
        __half* __restrict__ z) {
    int b = blockIdx.z, h = blockIdx.y, l0 = blockIdx.x * 64;
    __shared__ float tile[64][65];
    __shared__ float rs1[4][64], rs2[4][64];
    __shared__ float smean[64], sinv[64];
    int tid = threadIdx.x;
    size_t ybase = ((size_t)(b * H_ + h) * L_ + l0) * N_;

    #pragma unroll
    for (int i = 0; i < 16; i++) {
        int id = tid + i * 256;
        int row = id >> 6, col = id & 63;
        tile[col][row] = yy[ybase + (size_t)row * N_ + col];
    }
    __syncthreads();
    {
        int l = tid & 63, part = tid >> 6;
        float s1 = 0.f, s2 = 0.f;
        #pragma unroll
        for (int i = 0; i < 16; i++) {
            float v = tile[part * 16 + i][l];
            s1 += v; s2 += v * v;
        }
        rs1[part][l] = s1; rs2[part][l] = s2;
    }
    __syncthreads();
    if (tid < 64) {
        float s1 = rs1[0][tid] + rs1[1][tid] + rs1[2][tid] + rs1[3][tid];
        float s2 = rs2[0][tid] + rs2[1][tid] + rs2[2][tid] + rs2[3][tid];
        float mean = s1 * (1.f / 64);
        float var = s2 * (1.f / 64) - mean * mean;
        smean[tid] = mean;
        sinv[tid] = rsqrtf(var + 1e-5f);
    }
    __syncthreads();

    int n = tid >> 2, lq = tid & 3;
    int c = h * 64 + n;
    float lw = lnw[c], lb = lnb[c];
    #pragma unroll
    for (int q = 0; q < 16; q++) {
        int l = lq * 16 + q;
        size_t rofs = ((size_t)b * L_ + l0 + l) * C_ + c;
        float v = ((tile[n][l] - smean[l]) * sinv[l] * lw + lb) * gate[rofs];
        z[rofs] = __float2half(v);
    }
}

// ---------------- residual + rms ----------------
__global__ void __launch_bounds__(128)
resid_rms_k(const float* __restrict__ img, const float* __restrict__ txt,
            const float* __restrict__ attn, const float* __restrict__ mod,
            const float* __restrict__ w2i, const float* __restrict__ w2t,
            float* __restrict__ img1, float* __restrict__ txt1,
            float* __restrict__ himg, float* __restrict__ htxt) {
    int b = blockIdx.y;
    int l = blockIdx.x * 128 + threadIdx.x;
    int s, li, Ls;
    const float* src; float* d1; float* dh; const float* rw;
    if (l < LI_) { s = 0; li = l;       Ls = LI_; src = img; d1 = img1; dh = himg; rw = w2i; }
    else         { s = 1; li = l - LI_; Ls = LT_; src = txt; d1 = txt1; dh = htxt; rw = w2t; }
    const float* mb = mod + (s * B_ + b) * 6 * C_;
    const float* ap = attn + (size_t)b * C_ * L_ + l;
    const float* sp = src + (size_t)b * C_ * Ls + li;
    float* p1 = d1 + (size_t)b * C_ * Ls + li;
    float* ph = dh + (size_t)b * C_ * Ls + li;
    float ss = 0.f;
    #pragma unroll 4
    for (int c = 0; c < C_; c++) {
        float v = sp[(size_t)c * Ls] + mb[2 * C_ + c] * ap[(size_t)c * L_];
        p1[(size_t)c * Ls] = v;
        ss += v * v;
    }
    float inv = rsqrtf(ss * (1.f / C_) + 1e-6f);
    #pragma unroll 4
    for (int c = 0; c < C_; c++) {
        float v = p1[(size_t)c * Ls];
        ph[(size_t)c * Ls] = v * inv * rw[c] * (1.f + mb[4 * C_ + c]) + mb[3 * C_ + c];
    }
}

// ---------------- host ----------------
static float* symaddr(const void* s) {
    void* p = nullptr;
    cudaGetSymbolAddress(&p, s);
    return (float*)p;
}
static __half* symaddrh(const void* s) {
    void* p = nullptr;
    cudaGetSymbolAddress(&p, s);
    return (__half*)p;
}

extern "C" void kernel_launch(void* const* d_in, const int* in_sizes, int n_in,
                              void* d_out, int out_size) {
    const float* img   = (const float*)d_in[0];
    const float* txt   = (const float*)d_in[1];
    const float* cond  = (const float*)d_in[2];
    const float* Wmi   = (const float*)d_in[3];
    const float* bmi   = (const float*)d_in[4];
    const float* Wmt   = (const float*)d_in[5];
    const float* bmt   = (const float*)d_in[6];
    const float* rmsi  = (const float*)d_in[7];
    const float* rmst  = (const float*)d_in[8];
    const float* rmsi2 = (const float*)d_in[9];
    const float* rmst2 = (const float*)d_in[10];
    const float* mur   = (const float*)d_in[11];
    const float* muk   = (const float*)d_in[12];
    const float* muv   = (const float*)d_in[13];
    const float* mug   = (const float*)d_in[14];
    const float* Wr    = (const float*)d_in[15];
    const float* Wk    = (const float*)d_in[16];
    const float* Wv    = (const float*)d_in[17];
    const float* Wg    = (const float*)d_in[18];
    const float* Wo    = (const float*)d_in[19];
    const float* td    = (const float*)d_in[20];
    const float* tf    = (const float*)d_in[21];
    const float* lnw   = (const float*)d_in[22];
    const float* lnb   = (const float*)d_in[23];
    const float* fi1   = (const float*)d_in[24];
    const float* fi2   = (const float*)d_in[25];
    const float* ft1   = (const float*)d_in[26];
    const float* ft2   = (const float*)d_in[27];

    float* p_scond = symaddr(g_scond);
    float* p_mod   = symaddr(g_mod);
    float* p_x     = symaddr(g_x);
    float* p_gate  = symaddr(g_gate);
    float* p_r     = symaddr(g_r);
    float* p_k     = symaddr(g_k);
    float* p_v     = symaddr(g_v);
    float* p_y     = symaddr(g_y);
    float* p_attn  = symaddr(g_attn);
    float* p_img1  = symaddr(g_img1);
    float* p_txt1  = symaddr(g_txt1);
    float* p_himg  = symaddr(g_himg);
    float* p_htxt  = symaddr(g_htxt);

    __half* pArkvg = symaddrh(g_Arkvg);
    __half* pAwo   = symaddrh(g_Awo);
    __half* pAfi1  = symaddrh(g_Afi1);
    __half* pAfi2  = symaddrh(g_Afi2);
    __half* pAft1  = symaddrh(g_Aft1);
    __half* pAft2  = symaddrh(g_Aft2);
    __half* pBx    = symaddrh(g_Bx);
    __half* pBz    = symaddrh(g_Bz);
    __half* pBhi   = symaddrh(g_Bhi);
    __half* pBht   = symaddrh(g_Bht);
    __half* pBmi   = symaddrh(g_Bmi);
    __half* pBmt   = symaddrh(g_Bmt);

    float* out_img = (float*)d_out;
    float* out_txt = out_img + IMGSZ;

    cudaFuncSetAttribute(gemm_mma<0>, cudaFuncAttributeMaxDynamicSharedMemorySize, GSMEM);
    cudaFuncSetAttribute(gemm_mma<1>, cudaFuncAttributeMaxDynamicSharedMemorySize, GSMEM);
    cudaFuncSetAttribute(gemm_mma<2>, cudaFuncAttributeMaxDynamicSharedMemorySize, GSMEM);
    cudaFuncSetAttribute(gemm_mma<3>, cudaFuncAttributeMaxDynamicSharedMemorySize, GSMEM);

    // launches 0-4 (profiled launch is #5 = rkvg GEMM)
    silu_cond_k<<<(B_ * C_ + 255) / 256, 256>>>(cond, p_scond);
    mod_k<<<(2 * 6 * C_) / 8, 256>>>(Wmi, bmi, Wmt, bmt, p_scond, p_mod);
    buildx_k<<<dim3(L_ / 128, B_), 128>>>(img, txt, rmsi, rmst, p_mod, p_x);
    wsplit2_rkvg_k<<<(4096 * 1024) / 256, 256>>>(Wr, Wk, Wv, Wg, mur, muk, muv, mug, pArkvg);
    asplit_shift_k<<<dim3(L_ / 32, C_ / 32, B_), 256>>>(p_x, pBx);

    // 5) fused rkvg GEMM
    gemm_mma<1><<<dim3(L_ / 128, 4096 / 128, B_), 256, GSMEM>>>(
        pArkvg, pBx, nullptr, nullptr, p_r, p_k, p_v, p_gate,
        nullptr, nullptr, 4096, 4096, 2048, L_);

    // remaining weight splits
    wsplit2_plain_k<<<(1024 * 1024) / 256, 256>>>(Wo,  pAwo,  1024, 1024);
    wsplit2_plain_k<<<(2048 * 1024) / 256, 256>>>(fi1, pAfi1, 2048, 1024);
    wsplit2_plain_k<<<(1024 * 2048) / 256, 256>>>(fi2, pAfi2, 1024, 2048);
    wsplit2_plain_k<<<(2048 * 1024) / 256, 256>>>(ft1, pAft1, 2048, 1024);
    wsplit2_plain_k<<<(1024 * 2048) / 256, 256>>>(ft2, pAft2, 1024, 2048);

    // scan
    scan_k<<<B_ * H_, 256>>>(p_r, p_k, p_v, td, tf, p_y);

    // groupnorm * gate -> fp16 (B,L,C)
    gnorm_k<<<dim3(L_ / 64, H_, B_), 256>>>(p_y, p_gate, lnw, lnb, pBz);

    // Wo GEMM -> attn (B,C,L)
    gemm_mma<0><<<dim3(L_ / 128, C_ / 128, B_), 256, GSMEM>>>(
        pAwo, pBz, p_attn, nullptr, nullptr, nullptr, nullptr, nullptr,
        nullptr, nullptr, C_, 2048, 1024, L_);

    // residual + rms
    resid_rms_k<<<dim3(L_ / 128, B_), 128>>>(img, txt, p_attn, p_mod, rmsi2, rmst2,
                                             p_img1, p_txt1, p_himg, p_htxt);

    // FFN img
    asplit1_k<<<dim3(LI_ / 32, C_ / 32, B_), 256>>>(p_himg, pBhi, C_, LI_);
    gemm_mma<2><<<dim3(LI_ / 128, HID_ / 128, B_), 256, GSMEM>>>(
        pAfi1, pBhi, nullptr, pBmi, nullptr, nullptr, nullptr, nullptr,
        nullptr, nullptr, HID_, 2048, 1024, LI_);
    gemm_mma<3><<<dim3(LI_ / 128, C_ / 128, B_), 256, GSMEM>>>(
        pAfi2, pBmi, out_img, nullptr, nullptr, nullptr, nullptr, nullptr,
        p_img1, p_mod + 5 * C_, C_, 4096, 2048, LI_);

    // FFN txt
    asplit1_k<<<dim3(LT_ / 32, C_ / 32, B_), 256>>>(p_htxt, pBht, C_, LT_);
    gemm_mma<2><<<dim3(LT_ / 128, HID_ / 128, B_), 256, GSMEM>>>(
        pAft1, pBht, nullptr, pBmt, nullptr, nullptr, nullptr, nullptr,
        nullptr, nullptr, HID_, 2048, 1024, LT_);
    gemm_mma<3><<<dim3(LT_ / 128, C_ / 128, B_), 256, GSMEM>>>(
        pAft2, pBmt, out_txt, nullptr, nullptr, nullptr, nullptr, nullptr,
        p_txt1, p_mod + B_ * 6 * C_ + 5 * C_, C_, 4096, 2048, LT_);
}

// round 9
// speedup vs baseline: 3.1923x; 1.3288x over previous
#include <cuda_runtime.h>
#include <cuda_fp16.h>
#include <math.h>
#include <stdint.h>

constexpr int B_  = 2;
constexpr int C_  = 1024;
constexpr int H_  = 16;
constexpr int N_  = 64;
constexpr int LI_ = 4096;
constexpr int LT_ = 512;
constexpr int L_  = LI_ + LT_;   // 4608
constexpr int HID_ = 2048;

constexpr size_t XSZ   = (size_t)B_ * C_ * L_;
constexpr size_t IMGSZ = (size_t)B_ * C_ * LI_;
constexpr size_t TXTSZ = (size_t)B_ * C_ * LT_;

// ---------------- static scratch ----------------
__device__ float g_mod[2 * B_ * 6 * C_];
__device__ float g_inv[B_ * L_];
__device__ float g_gate[XSZ];                        // silu(g) in (B,L,C)
__device__ float g_r[XSZ];                           // (B,H,L,N)
__device__ float g_k[XSZ];
__device__ float g_v[XSZ];
__device__ float g_y[XSZ];
__device__ float g_attn[XSZ];                        // (B,C,L)
__device__ float g_img1[IMGSZ];
__device__ float g_txt1[TXTSZ];
__device__ float g_himg[IMGSZ];
__device__ float g_htxt[TXTSZ];

// fp16 GEMM operands (single precision-level fp16, no split)
__device__ __half g_Arkvg[(size_t)4096 * 2048];      // [Wd | Ws]
__device__ __half g_Awo [(size_t)1024 * 1024];
__device__ __half g_Afi1[(size_t)2048 * 1024];
__device__ __half g_Afi2[(size_t)1024 * 2048];
__device__ __half g_Aft1[(size_t)2048 * 1024];
__device__ __half g_Aft2[(size_t)1024 * 2048];
__device__ __half g_Bx [(size_t)B_ * L_  * 2048];    // [x_l | x_{l-1}]
__device__ __half g_Bz [(size_t)B_ * L_  * 1024];
__device__ __half g_Bhi[(size_t)B_ * LI_ * 1024];
__device__ __half g_Bht[(size_t)B_ * LT_ * 1024];
__device__ __half g_Bmi[(size_t)B_ * LI_ * 2048];
__device__ __half g_Bmt[(size_t)B_ * LT_ * 2048];

// ---------------- helpers ----------------
__device__ __forceinline__ uint32_t smem_u32(const void* p) {
    uint32_t r;
    asm("{ .reg .u64 t; cvta.to.shared.u64 t, %1; cvt.u32.u64 %0, t; }" : "=r"(r) : "l"(p));
    return r;
}
__device__ __forceinline__ void cp16(uint32_t s, const void* g) {
    asm volatile("cp.async.cg.shared.global [%0], [%1], 16;" :: "r"(s), "l"(g));
}
__device__ __forceinline__ void ldsm4(uint32_t* r, uint32_t addr) {
    asm volatile("ldmatrix.sync.aligned.m8n8.x4.shared.b16 {%0,%1,%2,%3},[%4];"
                 : "=r"(r[0]), "=r"(r[1]), "=r"(r[2]), "=r"(r[3]) : "r"(addr));
}
__device__ __forceinline__ void mma16816(float* d, const uint32_t* a, const uint32_t* b) {
    asm volatile("mma.sync.aligned.m16n8k16.row.col.f32.f16.f16.f32 "
                 "{%0,%1,%2,%3},{%4,%5,%6,%7},{%8,%9},{%0,%1,%2,%3};"
                 : "+f"(d[0]), "+f"(d[1]), "+f"(d[2]), "+f"(d[3])
                 : "r"(a[0]), "r"(a[1]), "r"(a[2]), "r"(a[3]), "r"(b[0]), "r"(b[1]));
}

// ---------------- prep: modulation (silu inline) + rms sums ----------------
constexpr int MOD_BLOCKS = (2 * 6 * C_) / 8;     // 1536 blocks, 8 warps each
constexpr int RMS_BLOCKS = (B_ * L_) / 256;      // 36 blocks

__global__ void prep_k(const float* __restrict__ cond,
                       const float* __restrict__ Wimg, const float* __restrict__ bimg,
                       const float* __restrict__ Wtxt, const float* __restrict__ btxt,
                       const float* __restrict__ img, const float* __restrict__ txt,
                       float* __restrict__ modout, float* __restrict__ invout) {
    if (blockIdx.x < MOD_BLOCKS) {
        int gw = (blockIdx.x * 256 + threadIdx.x) >> 5;
        int lane = threadIdx.x & 31;
        int s = gw / (6 * C_), o = gw % (6 * C_);
        const float* Wp = (s ? Wtxt : Wimg) + (size_t)o * C_;
        float a0 = 0.f, a1 = 0.f;
        for (int c = lane; c < C_; c += 32) {
            float wv = Wp[c];
            float c0 = cond[c], c1 = cond[C_ + c];
            a0 += wv * (c0 / (1.f + expf(-c0)));
            a1 += wv * (c1 / (1.f + expf(-c1)));
        }
        #pragma unroll
        for (int off = 16; off; off >>= 1) {
            a0 += __shfl_down_sync(0xffffffffu, a0, off);
            a1 += __shfl_down_sync(0xffffffffu, a1, off);
        }
        if (lane == 0) {
            float bb = (s ? btxt : bimg)[o];
            modout[(s * B_ + 0) * 6 * C_ + o] = a0 + bb;
            modout[(s * B_ + 1) * 6 * C_ + o] = a1 + bb;
        }
    } else {
        int gid = (blockIdx.x - MOD_BLOCKS) * 256 + threadIdx.x;
        if (gid >= B_ * L_) return;
        int b = gid / L_, l = gid % L_;
        const float* src; int Ls, li;
        if (l < LI_) { src = img; Ls = LI_; li = l; }
        else         { src = txt; Ls = LT_; li = l - LI_; }
        const float* sp = src + (size_t)b * C_ * Ls + li;
        float ss = 0.f;
        #pragma unroll 8
        for (int c = 0; c < C_; c++) { float v = sp[(size_t)c * Ls]; ss += v * v; }
        invout[gid] = rsqrtf(ss * (1.f / C_) + 1e-6f);
    }
}

// ---------------- weight packs (single fp16) ----------------
__global__ void wsplit1_rkvg_k(const float* __restrict__ Wr, const float* __restrict__ Wk,
                               const float* __restrict__ Wv, const float* __restrict__ Wg,
                               const float* __restrict__ mur, const float* __restrict__ muk,
                               const float* __restrict__ muv, const float* __restrict__ mug,
                               __half* __restrict__ A) {
    size_t idx = (size_t)blockIdx.x * 256 + threadIdx.x;
    if (idx >= (size_t)4096 * 1024) return;
    int m = (int)(idx >> 10), c = (int)(idx & 1023);
    int p = m >> 10, mr = m & 1023;
    const float* W = (p == 0) ? Wr : (p == 1) ? Wk : (p == 2) ? Wv : Wg;
    const float* mu = (p == 0) ? mur : (p == 1) ? muk : (p == 2) ? muv : mug;
    float mm = mu[c];
    float wv = W[(size_t)mr * C_ + c];
    __half* o = A + (size_t)m * 2048 + c;
    o[0]    = __float2half(wv * (1.f - mm));
    o[1024] = __float2half(wv * mm);
}

__global__ void wsplit1_plain_k(const float* __restrict__ W, __half* __restrict__ A,
                                size_t total) {
    size_t idx = (size_t)blockIdx.x * 256 + threadIdx.x;
    if (idx < total) A[idx] = __float2half(W[idx]);
}

// ---------------- Bx build: rms-modulate + transpose + shift pack ----------------
__global__ void __launch_bounds__(256)
bxbuild_k(const float* __restrict__ img, const float* __restrict__ txt,
          const float* __restrict__ rmswi, const float* __restrict__ rmswt,
          const float* __restrict__ mod, const float* __restrict__ inv,
          __half* __restrict__ out) {
    __shared__ float tile[32][33];
    int b = blockIdx.z, c0 = blockIdx.y * 32, l0 = blockIdx.x * 32;
    int tx = threadIdx.x & 31, wy = threadIdx.x >> 5;
    const float* src; const float* rw; int Ls, li0, s;
    if (l0 < LI_) { src = img; Ls = LI_; li0 = l0;       s = 0; rw = rmswi; }
    else          { src = txt; Ls = LT_; li0 = l0 - LI_; s = 1; rw = rmswt; }
    const float* ip = src + ((size_t)b * C_ + c0) * Ls + li0;
    #pragma unroll
    for (int i = 0; i < 4; i++) { int c = wy + i * 8; tile[c][tx] = ip[(size_t)c * Ls + tx]; }
    __syncthreads();
    const float* mb = mod + (s * B_ + b) * 6 * C_;
    int c = c0 + tx;
    float rwc = rw[c];
    float sc1 = 1.f + mb[C_ + c];
    float sh1 = mb[c];
    #pragma unroll
    for (int i = 0; i < 4; i++) {
        int lrel = wy + i * 8;
        int l = l0 + lrel;
        float iv = inv[b * L_ + l];
        float v = tile[tx][lrel] * iv * rwc * sc1 + sh1;
        __half hv = __float2half(v);
        out[((size_t)b * L_ + l) * 2048 + c] = hv;
        if (l + 1 < L_)
            out[((size_t)b * L_ + l + 1) * 2048 + 1024 + c] = hv;
        if (l == 0)
            out[((size_t)b * L_) * 2048 + 1024 + c] = __float2half(0.f);
    }
}

// ---------------- activation transpose (fp32 -> fp16 (B,L,CR)) ----------------
__global__ void __launch_bounds__(256)
asplit1_k(const float* __restrict__ in, __half* __restrict__ out, int CR, int LL) {
    __shared__ float tile[32][33];
    int b = blockIdx.z, c0 = blockIdx.y * 32, l0 = blockIdx.x * 32;
    int tx = threadIdx.x & 31, wy = threadIdx.x >> 5;
    const float* ip = in + ((size_t)b * CR + c0) * LL + l0;
    #pragma unroll
    for (int i = 0; i < 4; i++) { int c = wy + i * 8; tile[c][tx] = ip[(size_t)c * LL + tx]; }
    __syncthreads();
    #pragma unroll
    for (int i = 0; i < 4; i++) {
        int l = wy + i * 8;
        out[((size_t)b * LL + l0 + l) * CR + (c0 + tx)] = __float2half(tile[tx][l]);
    }
}

// ---------------- mma.sync GEMM (K = true K, fp16 operands) ----------------
constexpr int STG = 18432;            // 128 rows * 144B
constexpr int GSMEM = 4 * STG;

template <int MODE>
__global__ void __launch_bounds__(256, 2)
gemm_mma(const __half* __restrict__ A, const __half* __restrict__ Bm,
         float* __restrict__ Y, __half* __restrict__ Yh,
         float* __restrict__ ro, float* __restrict__ ko, float* __restrict__ vo,
         float* __restrict__ go,
         const float* __restrict__ resid, const float* __restrict__ gmod,
         int M, int K, int Llen) {
    extern __shared__ __align__(16) char dsmem[];
    uint32_t sb = smem_u32(dsmem);
    int tid = threadIdx.x, lane = tid & 31, wid = tid >> 5;
    int wm = wid >> 2, wn = wid & 3;
    int b = blockIdx.z, l0 = blockIdx.x * 128, m0 = blockIdx.y * 128;
    const int NT = K >> 6;

    float acc[4][4][4] = {};
    const __half* Ag = A + (size_t)m0 * K;
    const __half* Bg = Bm + ((size_t)b * Llen + l0) * K;

    int r_ld = tid >> 1, seg = tid & 1;
    uint32_t soff = (uint32_t)(r_ld * 144 + seg * 64);
    const __half* Agr = Ag + (size_t)r_ld * K + seg * 32;
    const __half* Bgr = Bg + (size_t)r_ld * K + seg * 32;

    #pragma unroll
    for (int j = 0; j < 4; j++) {
        cp16(sb + soff + j * 16,             Agr + j * 8);
        cp16(sb + 2 * STG + soff + j * 16,   Bgr + j * 8);
    }
    asm volatile("cp.async.commit_group;");

    for (int it = 0; it < NT; it++) {
        int q = it & 1;
        if (it + 1 < NT) {
            int qq = q ^ 1;
            int ka = (it + 1) * 64;
            #pragma unroll
            for (int j = 0; j < 4; j++) {
                cp16(sb + qq * STG + soff + j * 16,           Agr + ka + j * 8);
                cp16(sb + 2 * STG + qq * STG + soff + j * 16, Bgr + ka + j * 8);
            }
            asm volatile("cp.async.commit_group;");
            asm volatile("cp.async.wait_group 1;");
        } else {
            asm volatile("cp.async.wait_group 0;");
        }
        __syncthreads();

        uint32_t baseA = sb + q * STG, baseB = sb + 2 * STG + q * STG;
        #pragma unroll
        for (int kk = 0; kk < 4; kk++) {
            uint32_t a[4][4], bq[2][4];
            #pragma unroll
            for (int ma = 0; ma < 4; ma++)
                ldsm4(a[ma], baseA + (wm * 64 + ma * 16 + (lane & 15)) * 144
                              + kk * 32 + (lane >> 4) * 16);
            #pragma unroll
            for (int nb = 0; nb < 2; nb++)
                ldsm4(bq[nb], baseB + (wn * 32 + nb * 16 + (lane & 7) + ((lane >> 4) & 1) * 8) * 144
                               + kk * 32 + ((lane >> 3) & 1) * 16);
            #pragma unroll
            for (int ma = 0; ma < 4; ma++)
                #pragma unroll
                for (int na = 0; na < 4; na++)
                    mma16816(acc[ma][na], a[ma], &bq[na >> 1][(na & 1) * 2]);
        }
        __syncthreads();
    }

    if (MODE == 0 || MODE == 3) {
        #pragma unroll
        for (int ma = 0; ma < 4; ma++) {
            #pragma unroll
            for (int hf = 0; hf < 2; hf++) {
                int m = m0 + wm * 64 + ma * 16 + (lane >> 2) + hf * 8;
                size_t ybase = ((size_t)b * M + m) * Llen;
                float gm = 0.f;
                if (MODE == 3) gm = gmod[b * 6 * C_ + m];
                #pragma unroll
                for (int na = 0; na < 4; na++) {
                    int col = l0 + wn * 32 + na * 8 + 2 * (lane & 3);
                    float v0 = acc[ma][na][hf * 2], v1 = acc[ma][na][hf * 2 + 1];
                    if (MODE == 3) {
                        float2 rr = *(const float2*)(resid + ybase + col);
                        v0 = rr.x + gm * v0;
                        v1 = rr.y + gm * v1;
                    }
                    *(float2*)(Y + ybase + col) = make_float2(v0, v1);
                }
            }
        }
    } else if (MODE == 1) {
        float* st = (float*)dsmem;
        int part = m0 >> 10;
        int c0 = m0 & 1023;
        #pragma unroll
        for (int ma = 0; ma < 4; ma++)
            #pragma unroll
            for (int na = 0; na < 4; na++)
                #pragma unroll
                for (int e = 0; e < 4; e++) {
                    int hf = e >> 1, j = e & 1;
                    int m = wm * 64 + ma * 16 + (lane >> 2) + hf * 8;
                    int l = wn * 32 + na * 8 + 2 * (lane & 3) + j;
                    float v = acc[ma][na][hf * 2 + j];
                    if (part == 3) v = v / (1.f + expf(-v));
                    st[l * 132 + m] = v;
                }
        __syncthreads();
        int l = tid >> 1, sg = tid & 1;
        const float* sp = st + l * 132 + sg * 64;
        if (part < 3) {
            float* outb = (part == 0) ? ro : (part == 1) ? ko : vo;
            int c = c0 + sg * 64;
            float* op = outb + ((size_t)(b * H_ + (c >> 6)) * L_ + l0 + l) * 64;
            #pragma unroll
            for (int j = 0; j < 64; j += 4)
                *(float4*)(op + j) = *(const float4*)(sp + j);
        } else {
            float* op = go + ((size_t)b * L_ + l0 + l) * C_ + c0 + sg * 64;
            #pragma unroll
            for (int j = 0; j < 64; j += 4)
                *(float4*)(op + j) = *(const float4*)(sp + j);
        }
    } else { // MODE 2: gelu -> fp16 (B,L,M)
        __half* st = (__half*)dsmem;
        #pragma unroll
        for (int ma = 0; ma < 4; ma++)
            #pragma unroll
            for (int na = 0; na < 4; na++)
                #pragma unroll
                for (int e = 0; e < 4; e++) {
                    int hf = e >> 1, j = e & 1;
                    int m = wm * 64 + ma * 16 + (lane >> 2) + hf * 8;
                    int l = wn * 32 + na * 8 + 2 * (lane & 3) + j;
                    float v = acc[ma][na][hf * 2 + j];
                    float t = 0.7978845608f * (v + 0.044715f * v * v * v);
                    v = 0.5f * v * (1.f + tanhf(t));
                    st[l * 136 + m] = __float2half(v);
                }
        __syncthreads();
        int l = tid >> 1, sg = tid & 1;
        const uint4* sp = (const uint4*)(st + l * 136 + sg * 64);
        uint4* op = (uint4*)(Yh + ((size_t)b * Llen + l0 + l) * M + m0 + sg * 64);
        #pragma unroll
        for (int j = 0; j < 8; j++) op[j] = sp[j];
    }
}

// ---------------- RWKV scan: chunked cp.async + shuffle reductions ----------------
constexpr int SCH = 16;
__global__ void __launch_bounds__(256)
scan_k(const float* __restrict__ rr, const float* __restrict__ kk,
       const float* __restrict__ vv, const float* __restrict__ td,
       const float* __restrict__ tf, float* __restrict__ yy) {
    __shared__ __align__(16) float rs[2][SCH * 64];
    __shared__ __align__(16) float ks[2][SCH * 64];
    __shared__ __align__(16) float vs[2][SCH * 64];
    int bh = blockIdx.x;
    int h = bh & (H_ - 1);
    int tid = threadIdx.x;
    int m = tid >> 2, ns = tid & 3;
    size_t base = (size_t)bh * L_ * N_;

    float S[16], w[16], u[16];
    #pragma unroll
    for (int i = 0; i < 16; i++) {
        int n = ns * 16 + i;
        w[i] = expf(-expf(td[h * N_ + n]));
        u[i] = tf[h * N_ + n];
        S[i] = 0.f;
    }

    uint32_t sr = smem_u32(rs), sk = smem_u32(ks), sv = smem_u32(vs);
    const int NCH = L_ / SCH;
    uint32_t toff = (uint32_t)tid * 16;

    cp16(sr + toff, rr + base + tid * 4);
    cp16(sk + toff, kk + base + tid * 4);
    cp16(sv + toff, vv + base + tid * 4);
    asm volatile("cp.async.commit_group;");
    asm volatile("cp.async.wait_group 0;");
    __syncthreads();

    for (int ch = 0; ch < NCH; ch++) {
        int q = ch & 1;
        if (ch + 1 < NCH) {
            uint32_t dst = (uint32_t)((q ^ 1) * SCH * 64 * 4) + toff;
            size_t gof = base + (size_t)(ch + 1) * SCH * 64 + tid * 4;
            cp16(sr + dst, rr + gof);
            cp16(sk + dst, kk + gof);
            cp16(sv + dst, vv + gof);
            asm volatile("cp.async.commit_group;");
        }
        const float* rb = rs[q];
        const float* kb = ks[q];
        const float* vb = vs[q];
        size_t yof = base + (size_t)ch * SCH * 64 + m;
        #pragma unroll 4
        for (int s = 0; s < SCH; s++) {
            const float* rp = rb + s * 64 + ns * 16;
            const float* kp = kb + s * 64 + ns * 16;
            float vm = vb[s * 64 + m];
            float t = 0.f, qq = 0.f;
            #pragma unroll
            for (int i = 0; i < 16; i += 4) {
                float4 r4 = *(const float4*)(rp + i);
                float4 k4 = *(const float4*)(kp + i);
                float rv[4] = {r4.x, r4.y, r4.z, r4.w};
                float kv[4] = {k4.x, k4.y, k4.z, k4.w};
                #pragma unroll
                for (int j = 0; j < 4; j++) {
                    int i2 = i + j;
                    t += rv[j] * S[i2];
                    qq += rv[j] * u[i2] * kv[j];
                    S[i2] = w[i2] * S[i2] + kv[j] * vm;
                }
            }
            t  += __shfl_xor_sync(0xffffffffu, t, 1);
            t  += __shfl_xor_sync(0xffffffffu, t, 2);
            qq += __shfl_xor_sync(0xffffffffu, qq, 1);
            qq += __shfl_xor_sync(0xffffffffu, qq, 2);
            if (ns == 0) yy[yof + (size_t)s * 64] = t + qq * vm;
        }
        if (ch + 1 < NCH) asm volatile("cp.async.wait_group 0;");
        __syncthreads();
    }
}

// ---------------- groupnorm * ln_x * gate -> fp16 (B,L,C) ----------------
__global__ void __launch_bounds__(256)
gnorm_k(const float* __restrict__ yy, const float* __restrict__ gate,
        const float* __restrict__ lnw, const float* __restrict__ lnb,
        __half* __restrict__ z) {
    int b = blockIdx.z, h = blockIdx.y, l0 = blockIdx.x * 64;
    __shared__ float tile[64][65];
    __shared__ float rs1[4][64], rs2[4][64];
    __shared__ float smean[64], sinv[64];
    int tid = threadIdx.x;
    size_t ybase = ((size_t)(b * H_ + h) * L_ + l0) * N_;

    #pragma unroll
    for (int i = 0; i < 16; i++) {
        int id = tid + i * 256;
        int row = id >> 6, col = id & 63;
        tile[col][row] = yy[ybase + (size_t)row * N_ + col];
    }
    __syncthreads();
    {
        int l = tid & 63, part = tid >> 6;
        float s1 = 0.f, s2 = 0.f;
        #pragma unroll
        for (int i = 0; i < 16; i++) {
            float v = tile[part * 16 + i][l];
            s1 += v; s2 += v * v;
        }
        rs1[part][l] = s1; rs2[part][l] = s2;
    }
    __syncthreads();
    if (tid < 64) {
        float s1 = rs1[0][tid] + rs1[1][tid] + rs1[2][tid] + rs1[3][tid];
        float s2 = rs2[0][tid] + rs2[1][tid] + rs2[2][tid] + rs2[3][tid];
        float mean = s1 * (1.f / 64);
        float var = s2 * (1.f / 64) - mean * mean;
        smean[tid] = mean;
        sinv[tid] = rsqrtf(var + 1e-5f);
    }
    __syncthreads();

    int n = tid >> 2, lq = tid & 3;
    int c = h * 64 + n;
    float lw = lnw[c], lb = lnb[c];
    #pragma unroll
    for (int q = 0; q < 16; q++) {
        int l = lq * 16 + q;
        size_t rofs = ((size_t)b * L_ + l0 + l) * C_ + c;
        float v = ((tile[n][l] - smean[l]) * sinv[l] * lw + lb) * gate[rofs];
        z[rofs] = __float2half(v);
    }
}

// ---------------- residual + rms ----------------
__global__ void __launch_bounds__(128)
resid_rms_k(const float* __restrict__ img, const float* __restrict__ txt,
            const float* __restrict__ attn, const float* __restrict__ mod,
            const float* __restrict__ w2i, const float* __restrict__ w2t,
            float* __restrict__ img1, float* __restrict__ txt1,
            float* __restrict__ himg, float* __restrict__ htxt) {
    int b = blockIdx.y;
    int l = blockIdx.x * 128 + threadIdx.x;
    int s, li, Ls;
    const float* src; float* d1; float* dh; const float* rw;
    if (l < LI_) { s = 0; li = l;       Ls = LI_; src = img; d1 = img1; dh = himg; rw = w2i; }
    else         { s = 1; li = l - LI_; Ls = LT_; src = txt; d1 = txt1; dh = htxt; rw = w2t; }
    const float* mb = mod + (s * B_ + b) * 6 * C_;
    const float* ap = attn + (size_t)b * C_ * L_ + l;
    const float* sp = src + (size_t)b * C_ * Ls + li;
    float* p1 = d1 + (size_t)b * C_ * Ls + li;
    float* ph = dh + (size_t)b * C_ * Ls + li;
    float ss = 0.f;
    #pragma unroll 4
    for (int c = 0; c < C_; c++) {
        float v = sp[(size_t)c * Ls] + mb[2 * C_ + c] * ap[(size_t)c * L_];
        p1[(size_t)c * Ls] = v;
        ss += v * v;
    }
    float inv = rsqrtf(ss * (1.f / C_) + 1e-6f);
    #pragma unroll 4
    for (int c = 0; c < C_; c++) {
        float v = p1[(size_t)c * Ls];
        ph[(size_t)c * Ls] = v * inv * rw[c] * (1.f + mb[4 * C_ + c]) + mb[3 * C_ + c];
    }
}

// ---------------- host ----------------
static float* symaddr(const void* s) {
    void* p = nullptr;
    cudaGetSymbolAddress(&p, s);
    return (float*)p;
}
static __half* symaddrh(const void* s) {
    void* p = nullptr;
    cudaGetSymbolAddress(&p, s);
    return (__half*)p;
}

extern "C" void kernel_launch(void* const* d_in, const int* in_sizes, int n_in,
                              void* d_out, int out_size) {
    const float* img   = (const float*)d_in[0];
    const float* txt   = (const float*)d_in[1];
    const float* cond  = (const float*)d_in[2];
    const float* Wmi   = (const float*)d_in[3];
    const float* bmi   = (const float*)d_in[4];
    const float* Wmt   = (const float*)d_in[5];
    const float* bmt   = (const float*)d_in[6];
    const float* rmsi  = (const float*)d_in[7];
    const float* rmst  = (const float*)d_in[8];
    const float* rmsi2 = (const float*)d_in[9];
    const float* rmst2 = (const float*)d_in[10];
    const float* mur   = (const float*)d_in[11];
    const float* muk   = (const float*)d_in[12];
    const float* muv   = (const float*)d_in[13];
    const float* mug   = (const float*)d_in[14];
    const float* Wr    = (const float*)d_in[15];
    const float* Wk    = (const float*)d_in[16];
    const float* Wv    = (const float*)d_in[17];
    const float* Wg    = (const float*)d_in[18];
    const float* Wo    = (const float*)d_in[19];
    const float* td    = (const float*)d_in[20];
    const float* tf    = (const float*)d_in[21];
    const float* lnw   = (const float*)d_in[22];
    const float* lnb   = (const float*)d_in[23];
    const float* fi1   = (const float*)d_in[24];
    const float* fi2   = (const float*)d_in[25];
    const float* ft1   = (const float*)d_in[26];
    const float* ft2   = (const float*)d_in[27];

    float* p_mod   = symaddr(g_mod);
    float* p_inv   = symaddr(g_inv);
    float* p_gate  = symaddr(g_gate);
    float* p_r     = symaddr(g_r);
    float* p_k     = symaddr(g_k);
    float* p_v     = symaddr(g_v);
    float* p_y     = symaddr(g_y);
    float* p_attn  = symaddr(g_attn);
    float* p_img1  = symaddr(g_img1);
    float* p_txt1  = symaddr(g_txt1);
    float* p_himg  = symaddr(g_himg);
    float* p_htxt  = symaddr(g_htxt);

    __half* pArkvg = symaddrh(g_Arkvg);
    __half* pAwo   = symaddrh(g_Awo);
    __half* pAfi1  = symaddrh(g_Afi1);
    __half* pAfi2  = symaddrh(g_Afi2);
    __half* pAft1  = symaddrh(g_Aft1);
    __half* pAft2  = symaddrh(g_Aft2);
    __half* pBx    = symaddrh(g_Bx);
    __half* pBz    = symaddrh(g_Bz);
    __half* pBhi   = symaddrh(g_Bhi);
    __half* pBht   = symaddrh(g_Bht);
    __half* pBmi   = symaddrh(g_Bmi);
    __half* pBmt   = symaddrh(g_Bmt);

    float* out_img = (float*)d_out;
    float* out_txt = out_img + IMGSZ;

    cudaFuncSetAttribute(gemm_mma<0>, cudaFuncAttributeMaxDynamicSharedMemorySize, GSMEM);
    cudaFuncSetAttribute(gemm_mma<1>, cudaFuncAttributeMaxDynamicSharedMemorySize, GSMEM);
    cudaFuncSetAttribute(gemm_mma<2>, cudaFuncAttributeMaxDynamicSharedMemorySize, GSMEM);
    cudaFuncSetAttribute(gemm_mma<3>, cudaFuncAttributeMaxDynamicSharedMemorySize, GSMEM);

    // 0) fused modulation + rms sums
    prep_k<<<MOD_BLOCKS + RMS_BLOCKS, 256>>>(cond, Wmi, bmi, Wmt, bmt, img, txt,
                                             p_mod, p_inv);
    // 1) rkvg weight pack
    wsplit1_rkvg_k<<<(4096 * 1024) / 256, 256>>>(Wr, Wk, Wv, Wg, mur, muk, muv, mug, pArkvg);
    // 2) Bx build (rms-mod + transpose + shift)
    bxbuild_k<<<dim3(L_ / 32, C_ / 32, B_), 256>>>(img, txt, rmsi, rmst, p_mod, p_inv, pBx);
    // 3) fused rkvg GEMM  (profiled launch)
    gemm_mma<1><<<dim3(L_ / 128, 4096 / 128, B_), 256, GSMEM>>>(
        pArkvg, pBx, nullptr, nullptr, p_r, p_k, p_v, p_gate,
        nullptr, nullptr, 4096, 2048, L_);

    // remaining weight packs
    wsplit1_plain_k<<<(1024 * 1024) / 256, 256>>>(Wo,  pAwo,  (size_t)1024 * 1024);
    wsplit1_plain_k<<<(2048 * 1024) / 256, 256>>>(fi1, pAfi1, (size_t)2048 * 1024);
    wsplit1_plain_k<<<(1024 * 2048) / 256, 256>>>(fi2, pAfi2, (size_t)1024 * 2048);
    wsplit1_plain_k<<<(2048 * 1024) / 256, 256>>>(ft1, pAft1, (size_t)2048 * 1024);
    wsplit1_plain_k<<<(1024 * 2048) / 256, 256>>>(ft2, pAft2, (size_t)1024 * 2048);

    // scan
    scan_k<<<B_ * H_, 256>>>(p_r, p_k, p_v, td, tf, p_y);

    // groupnorm * gate -> fp16 (B,L,C)
    gnorm_k<<<dim3(L_ / 64, H_, B_), 256>>>(p_y, p_gate, lnw, lnb, pBz);

    // Wo GEMM -> attn (B,C,L)
    gemm_mma<0><<<dim3(L_ / 128, C_ / 128, B_), 256, GSMEM>>>(
        pAwo, pBz, p_attn, nullptr, nullptr, nullptr, nullptr, nullptr,
        nullptr, nullptr, C_, 1024, L_);

    // residual + rms
    resid_rms_k<<<dim3(L_ / 128, B_), 128>>>(img, txt, p_attn, p_mod, rmsi2, rmst2,
                                             p_img1, p_txt1, p_himg, p_htxt);

    // FFN img
    asplit1_k<<<dim3(LI_ / 32, C_ / 32, B_), 256>>>(p_himg, pBhi, C_, LI_);
    gemm_mma<2><<<dim3(LI_ / 128, HID_ / 128, B_), 256, GSMEM>>>(
        pAfi1, pBhi, nullptr, pBmi, nullptr, nullptr, nullptr, nullptr,
        nullptr, nullptr, HID_, 1024, LI_);
    gemm_mma<3><<<dim3(LI_ / 128, C_ / 128, B_), 256, GSMEM>>>(
        pAfi2, pBmi, out_img, nullptr, nullptr, nullptr, nullptr, nullptr,
        p_img1, p_mod + 5 * C_, C_, 2048, LI_);

    // FFN txt
    asplit1_k<<<dim3(LT_ / 32, C_ / 32, B_), 256>>>(p_htxt, pBht, C_, LT_);
    gemm_mma<2><<<dim3(LT_ / 128, HID_ / 128, B_), 256, GSMEM>>>(
        pAft1, pBht, nullptr, pBmt, nullptr, nullptr, nullptr, nullptr,
        nullptr, nullptr, HID_, 1024, LT_);
    gemm_mma<3><<<dim3(LT_ / 128, C_ / 128, B_), 256, GSMEM>>>(
        pAft2, pBmt, out_txt, nullptr, nullptr, nullptr, nullptr, nullptr,
        p_txt1, p_mod + B_ * 6 * C_ + 5 * C_, C_, 2048, LT_);
}

// round 10
// speedup vs baseline: 4.2826x; 1.3416x over previous
#include <cuda_runtime.h>
#include <cuda_fp16.h>
#include <math.h>
#include <stdint.h>

constexpr int B_  = 2;
constexpr int C_  = 1024;
constexpr int H_  = 16;
constexpr int N_  = 64;
constexpr int LI_ = 4096;
constexpr int LT_ = 512;
constexpr int L_  = LI_ + LT_;   // 4608
constexpr int HID_ = 2048;

constexpr size_t XSZ   = (size_t)B_ * C_ * L_;
constexpr size_t IMGSZ = (size_t)B_ * C_ * LI_;
constexpr size_t TXTSZ = (size_t)B_ * C_ * LT_;

// ---------------- static scratch ----------------
__device__ float g_mod[2 * B_ * 6 * C_];
__device__ float g_inv[B_ * L_];
__device__ float g_gate[XSZ];                        // silu(g) in (B,L,C)
__device__ float g_r[XSZ];                           // (B,H,L,N)
__device__ float g_k[XSZ];
__device__ float g_v[XSZ];
__device__ float g_y[XSZ];
__device__ float g_attn[XSZ];                        // (B,C,L)
__device__ float g_img1[IMGSZ];
__device__ float g_txt1[TXTSZ];
__device__ float g_himg[IMGSZ];
__device__ float g_htxt[TXTSZ];

// fp16 GEMM operands
__device__ __half g_Arkvg[(size_t)4096 * 1024];      // [Wr;Wk;Wv;Wg]
__device__ __half g_Awo [(size_t)1024 * 1024];
__device__ __half g_Afi1[(size_t)2048 * 1024];
__device__ __half g_Afi2[(size_t)1024 * 2048];
__device__ __half g_Aft1[(size_t)2048 * 1024];
__device__ __half g_Aft2[(size_t)1024 * 2048];
__device__ __half g_Bx4[(size_t)4 * B_ * L_ * 1024]; // mixed inputs per part p
__device__ __half g_Bz [(size_t)B_ * L_  * 1024];
__device__ __half g_Bhi[(size_t)B_ * LI_ * 1024];
__device__ __half g_Bht[(size_t)B_ * LT_ * 1024];
__device__ __half g_Bmi[(size_t)B_ * LI_ * 2048];
__device__ __half g_Bmt[(size_t)B_ * LT_ * 2048];

// ---------------- helpers ----------------
__device__ __forceinline__ uint32_t smem_u32(const void* p) {
    uint32_t r;
    asm("{ .reg .u64 t; cvta.to.shared.u64 t, %1; cvt.u32.u64 %0, t; }" : "=r"(r) : "l"(p));
    return r;
}
__device__ __forceinline__ void cp16(uint32_t s, const void* g) {
    asm volatile("cp.async.cg.shared.global [%0], [%1], 16;" :: "r"(s), "l"(g));
}
__device__ __forceinline__ void ldsm4(uint32_t* r, uint32_t addr) {
    asm volatile("ldmatrix.sync.aligned.m8n8.x4.shared.b16 {%0,%1,%2,%3},[%4];"
                 : "=r"(r[0]), "=r"(r[1]), "=r"(r[2]), "=r"(r[3]) : "r"(addr));
}
__device__ __forceinline__ void mma16816(float* d, const uint32_t* a, const uint32_t* b) {
    asm volatile("mma.sync.aligned.m16n8k16.row.col.f32.f16.f16.f32 "
                 "{%0,%1,%2,%3},{%4,%5,%6,%7},{%8,%9},{%0,%1,%2,%3};"
                 : "+f"(d[0]), "+f"(d[1]), "+f"(d[2]), "+f"(d[3])
                 : "r"(a[0]), "r"(a[1]), "r"(a[2]), "r"(a[3]), "r"(b[0]), "r"(b[1]));
}

// ---------------- prep: modulation (silu inline) + rms sums ----------------
constexpr int MOD_BLOCKS = (2 * 6 * C_) / 8;
constexpr int RMS_BLOCKS = (B_ * L_) / 256;

__global__ void prep_k(const float* __restrict__ cond,
                       const float* __restrict__ Wimg, const float* __restrict__ bimg,
                       const float* __restrict__ Wtxt, const float* __restrict__ btxt,
                       const float* __restrict__ img, const float* __restrict__ txt,
                       float* __restrict__ modout, float* __restrict__ invout) {
    if (blockIdx.x < MOD_BLOCKS) {
        int gw = (blockIdx.x * 256 + threadIdx.x) >> 5;
        int lane = threadIdx.x & 31;
        int s = gw / (6 * C_), o = gw % (6 * C_);
        const float* Wp = (s ? Wtxt : Wimg) + (size_t)o * C_;
        float a0 = 0.f, a1 = 0.f;
        for (int c = lane; c < C_; c += 32) {
            float wv = Wp[c];
            float c0 = cond[c], c1 = cond[C_ + c];
            a0 += wv * (c0 / (1.f + expf(-c0)));
            a1 += wv * (c1 / (1.f + expf(-c1)));
        }
        #pragma unroll
        for (int off = 16; off; off >>= 1) {
            a0 += __shfl_down_sync(0xffffffffu, a0, off);
            a1 += __shfl_down_sync(0xffffffffu, a1, off);
        }
        if (lane == 0) {
            float bb = (s ? btxt : bimg)[o];
            modout[(s * B_ + 0) * 6 * C_ + o] = a0 + bb;
            modout[(s * B_ + 1) * 6 * C_ + o] = a1 + bb;
        }
    } else {
        int gid = (blockIdx.x - MOD_BLOCKS) * 256 + threadIdx.x;
        if (gid >= B_ * L_) return;
        int b = gid / L_, l = gid % L_;
        const float* src; int Ls, li;
        if (l < LI_) { src = img; Ls = LI_; li = l; }
        else         { src = txt; Ls = LT_; li = l - LI_; }
        const float* sp = src + (size_t)b * C_ * Ls + li;
        float ss = 0.f;
        #pragma unroll 8
        for (int c = 0; c < C_; c++) { float v = sp[(size_t)c * Ls]; ss += v * v; }
        invout[gid] = rsqrtf(ss * (1.f / C_) + 1e-6f);
    }
}

// ---------------- weight packs ----------------
// pack 4 rkvg weights (each 1024x1024) into A[4096][1024]
__global__ void wpack4_k(const float* __restrict__ Wr, const float* __restrict__ Wk,
                         const float* __restrict__ Wv, const float* __restrict__ Wg,
                         __half* __restrict__ A) {
    size_t idx = (size_t)blockIdx.x * 256 + threadIdx.x;
    if (idx >= (size_t)4 * 1024 * 1024) return;
    int p = (int)(idx >> 20);
    size_t rest = idx & 0xFFFFF;
    const float* W = (p == 0) ? Wr : (p == 1) ? Wk : (p == 2) ? Wv : Wg;
    A[idx] = __float2half(W[rest]);
}

__global__ void wsplit1_plain_k(const float* __restrict__ W, __half* __restrict__ A,
                                size_t total) {
    size_t idx = (size_t)blockIdx.x * 256 + threadIdx.x;
    if (idx < total) A[idx] = __float2half(W[idx]);
}

// ---------------- Bx4 build: rms-modulate + mix + transpose ----------------
__global__ void __launch_bounds__(256)
bxmix_k(const float* __restrict__ img, const float* __restrict__ txt,
        const float* __restrict__ rmswi, const float* __restrict__ rmswt,
        const float* __restrict__ mod, const float* __restrict__ inv,
        const float* __restrict__ mur, const float* __restrict__ muk,
        const float* __restrict__ muv, const float* __restrict__ mug,
        __half* __restrict__ out) {
    __shared__ float tileM[32][35];   // [c][j], j=0 -> l0-1, j=1+tx -> l0+tx
    int b = blockIdx.z, c0 = blockIdx.y * 32, l0 = blockIdx.x * 32;
    int tx = threadIdx.x & 31, wy = threadIdx.x >> 5;
    int s0 = (l0 < LI_) ? 0 : 1;
    const float* src0 = s0 ? txt : img;
    int Ls0 = s0 ? LT_ : LI_;
    int li0 = s0 ? l0 - LI_ : l0;
    const float* mb0 = mod + (s0 * B_ + b) * 6 * C_;
    const float* rw0 = s0 ? rmswt : rmswi;
    float ivl = inv[b * L_ + l0 + tx];
    #pragma unroll
    for (int i = 0; i < 4; i++) {
        int c = wy + i * 8;
        int cg = c0 + c;
        float raw = src0[((size_t)b * C_ + cg) * Ls0 + li0 + tx];
        tileM[c][1 + tx] = raw * ivl * rw0[cg] * (1.f + mb0[C_ + cg]) + mb0[cg];
        if (tx == 0) {
            float pv = 0.f;
            if (l0 > 0) {
                int lm = l0 - 1;
                int sm = (lm < LI_) ? 0 : 1;
                const float* srcm = sm ? txt : img;
                int Lsm = sm ? LT_ : LI_;
                int lim = sm ? lm - LI_ : lm;
                const float* mbm = mod + (sm * B_ + b) * 6 * C_;
                const float* rwm = sm ? rmswt : rmswi;
                float rm = srcm[((size_t)b * C_ + cg) * Lsm + lim];
                pv = rm * inv[b * L_ + lm] * rwm[cg] * (1.f + mbm[C_ + cg]) + mbm[cg];
            }
            tileM[c][0] = pv;
        }
    }
    __syncthreads();
    int cg = c0 + tx;
    float m_r = mur[cg], m_k = muk[cg], m_v = muv[cg], m_g = mug[cg];
    const size_t PSTR = (size_t)B_ * L_ * 1024;
    #pragma unroll
    for (int i = 0; i < 4; i++) {
        int lrel = wy + i * 8;
        float vl = tileM[tx][1 + lrel];
        float vp = tileM[tx][lrel];
        float d = vp - vl;
        size_t base = ((size_t)b * L_ + l0 + lrel) * 1024 + cg;
        out[base]            = __float2half(vl + m_r * d);
        out[base + PSTR]     = __float2half(vl + m_k * d);
        out[base + 2 * PSTR] = __float2half(vl + m_v * d);
        out[base + 3 * PSTR] = __float2half(vl + m_g * d);
    }
}

// ---------------- activation transpose (fp32 -> fp16 (B,L,CR)) ----------------
__global__ void __launch_bounds__(256)
asplit1_k(const float* __restrict__ in, __half* __restrict__ out, int CR, int LL) {
    __shared__ float tile[32][33];
    int b = blockIdx.z, c0 = blockIdx.y * 32, l0 = blockIdx.x * 32;
    int tx = threadIdx.x & 31, wy = threadIdx.x >> 5;
    const float* ip = in + ((size_t)b * CR + c0) * LL + l0;
    #pragma unroll
    for (int i = 0; i < 4; i++) { int c = wy + i * 8; tile[c][tx] = ip[(size_t)c * LL + tx]; }
    __syncthreads();
    #pragma unroll
    for (int i = 0; i < 4; i++) {
        int l = wy + i * 8;
        out[((size_t)b * LL + l0 + l) * CR + (c0 + tx)] = __float2half(tile[tx][l]);
    }
}

// ---------------- mma.sync GEMM: 3-stage cp.async pipeline ----------------
constexpr int STG = 18432;            // 128 rows * 144B per operand stage
constexpr int GSMEM = 6 * STG;        // 3 stages x (A,B)

// MODE 0: plain fp32 (B,M,L). MODE 1: rkvg (B from part p=m0>>10) -> r/k/v (B,H,L,N) + gate(B,L,C)
// MODE 2: gelu -> fp16 (B,L,M). MODE 3: resid + gate -> fp32 (B,M,L)
template <int MODE>
__global__ void __launch_bounds__(256, 2)
gemm_mma(const __half* __restrict__ A, const __half* __restrict__ Bm,
         float* __restrict__ Y, __half* __restrict__ Yh,
         float* __restrict__ ro, float* __restrict__ ko, float* __restrict__ vo,
         float* __restrict__ go,
         const float* __restrict__ resid, const float* __restrict__ gmod,
         int M, int K, int Llen) {
    extern __shared__ __align__(16) char dsmem[];
    uint32_t sb = smem_u32(dsmem);
    int tid = threadIdx.x, lane = tid & 31, wid = tid >> 5;
    int wm = wid >> 2, wn = wid & 3;
    int b = blockIdx.z, l0 = blockIdx.x * 128, m0 = blockIdx.y * 128;
    const int NT = K >> 6;

    float acc[4][4][4] = {};
    const __half* Ag = A + (size_t)m0 * K;
    const __half* Bg;
    if (MODE == 1) {
        int part = m0 >> 10;
        Bg = Bm + (((size_t)(part * B_ + b)) * Llen + l0) * K;
    } else {
        Bg = Bm + ((size_t)b * Llen + l0) * K;
    }

    int r_ld = tid >> 1, seg = tid & 1;
    uint32_t soff = (uint32_t)(r_ld * 144 + seg * 64);
    const __half* Agr = Ag + (size_t)r_ld * K + seg * 32;
    const __half* Bgr = Bg + (size_t)r_ld * K + seg * 32;

    // prologue: tiles 0,1 into stages 0,1
    #pragma unroll
    for (int t = 0; t < 2; t++) {
        uint32_t ao = sb + t * STG + soff;
        uint32_t bo = sb + 3 * STG + t * STG + soff;
        #pragma unroll
        for (int j = 0; j < 4; j++) {
            cp16(ao + j * 16, Agr + t * 64 + j * 8);
            cp16(bo + j * 16, Bgr + t * 64 + j * 8);
        }
        asm volatile("cp.async.commit_group;");
    }

    for (int it = 0; it < NT; it++) {
        if (it + 1 < NT) asm volatile("cp.async.wait_group 1;");
        else             asm volatile("cp.async.wait_group 0;");
        __syncthreads();
        if (it + 2 < NT) {
            int st = (it + 2) % 3;
            int ka = (it + 2) * 64;
            uint32_t ao = sb + st * STG + soff;
            uint32_t bo = sb + 3 * STG + st * STG + soff;
            #pragma unroll
            for (int j = 0; j < 4; j++) {
                cp16(ao + j * 16, Agr + ka + j * 8);
                cp16(bo + j * 16, Bgr + ka + j * 8);
            }
            asm volatile("cp.async.commit_group;");
        }
        uint32_t baseA = sb + (it % 3) * STG;
        uint32_t baseB = sb + 3 * STG + (it % 3) * STG;
        #pragma unroll
        for (int kk = 0; kk < 4; kk++) {
            uint32_t a[4][4], bq[2][4];
            #pragma unroll
            for (int ma = 0; ma < 4; ma++)
                ldsm4(a[ma], baseA + (wm * 64 + ma * 16 + (lane & 15)) * 144
                              + kk * 32 + (lane >> 4) * 16);
            #pragma unroll
            for (int nb = 0; nb < 2; nb++)
                ldsm4(bq[nb], baseB + (wn * 32 + nb * 16 + (lane & 7) + ((lane >> 4) & 1) * 8) * 144
                               + kk * 32 + ((lane >> 3) & 1) * 16);
            #pragma unroll
            for (int ma = 0; ma < 4; ma++)
                #pragma unroll
                for (int na = 0; na < 4; na++)
                    mma16816(acc[ma][na], a[ma], &bq[na >> 1][(na & 1) * 2]);
        }
    }

    if (MODE == 0 || MODE == 3) {
        #pragma unroll
        for (int ma = 0; ma < 4; ma++) {
            #pragma unroll
            for (int hf = 0; hf < 2; hf++) {
                int m = m0 + wm * 64 + ma * 16 + (lane >> 2) + hf * 8;
                size_t ybase = ((size_t)b * M + m) * Llen;
                float gm = 0.f;
                if (MODE == 3) gm = gmod[b * 6 * C_ + m];
                #pragma unroll
                for (int na = 0; na < 4; na++) {
                    int col = l0 + wn * 32 + na * 8 + 2 * (lane & 3);
                    float v0 = acc[ma][na][hf * 2], v1 = acc[ma][na][hf * 2 + 1];
                    if (MODE == 3) {
                        float2 rr = *(const float2*)(resid + ybase + col);
                        v0 = rr.x + gm * v0;
                        v1 = rr.y + gm * v1;
                    }
                    *(float2*)(Y + ybase + col) = make_float2(v0, v1);
                }
            }
        }
    } else if (MODE == 1) {
        __syncthreads();
        float* st = (float*)dsmem;
        int part = m0 >> 10;
        int c0 = m0 & 1023;
        #pragma unroll
        for (int ma = 0; ma < 4; ma++)
            #pragma unroll
            for (int na = 0; na < 4; na++)
                #pragma unroll
                for (int e = 0; e < 4; e++) {
                    int hf = e >> 1, j = e & 1;
                    int m = wm * 64 + ma * 16 + (lane >> 2) + hf * 8;
                    int l = wn * 32 + na * 8 + 2 * (lane & 3) + j;
                    float v = acc[ma][na][hf * 2 + j];
                    if (part == 3) v = v / (1.f + expf(-v));
                    st[l * 132 + m] = v;
                }
        __syncthreads();
        int l = tid >> 1, sg = tid & 1;
        const float* sp = st + l * 132 + sg * 64;
        if (part < 3) {
            float* outb = (part == 0) ? ro : (part == 1) ? ko : vo;
            int c = c0 + sg * 64;
            float* op = outb + ((size_t)(b * H_ + (c >> 6)) * L_ + l0 + l) * 64;
            #pragma unroll
            for (int j = 0; j < 64; j += 4)
                *(float4*)(op + j) = *(const float4*)(sp + j);
        } else {
            float* op = go + ((size_t)b * L_ + l0 + l) * C_ + c0 + sg * 64;
            #pragma unroll
            for (int j = 0; j < 64; j += 4)
                *(float4*)(op + j) = *(const float4*)(sp + j);
        }
    } else { // MODE 2: gelu -> fp16 (B,L,M)
        __syncthreads();
        __half* st = (__half*)dsmem;
        #pragma unroll
        for (int ma = 0; ma < 4; ma++)
            #pragma unroll
            for (int na = 0; na < 4; na++)
                #pragma unroll
                for (int e = 0; e < 4; e++) {
                    int hf = e >> 1, j = e & 1;
                    int m = wm * 64 + ma * 16 + (lane >> 2) + hf * 8;
                    int l = wn * 32 + na * 8 + 2 * (lane & 3) + j;
                    float v = acc[ma][na][hf * 2 + j];
                    float t = 0.7978845608f * (v + 0.044715f * v * v * v);
                    v = 0.5f * v * (1.f + tanhf(t));
                    st[l * 136 + m] = __float2half(v);
                }
        __syncthreads();
        int l = tid >> 1, sg = tid & 1;
        const uint4* sp = (const uint4*)(st + l * 136 + sg * 64);
        uint4* op = (uint4*)(Yh + ((size_t)b * Llen + l0 + l) * M + m0 + sg * 64);
        #pragma unroll
        for (int j = 0; j < 8; j++) op[j] = sp[j];
    }
}

// ---------------- RWKV scan: m-split x2, chunked cp.async + shuffle ----------------
constexpr int SCH = 16;
__global__ void __launch_bounds__(256)
scan_k(const float* __restrict__ rr, const float* __restrict__ kk,
       const float* __restrict__ vv, const float* __restrict__ td,
       const float* __restrict__ tf, float* __restrict__ yy) {
    __shared__ __align__(16) float rs[2][SCH * 64];
    __shared__ __align__(16) float ks[2][SCH * 64];
    __shared__ __align__(16) float vs[2][SCH * 64];
    int bh = blockIdx.x >> 1;
    int mh = blockIdx.x & 1;
    int h = bh & (H_ - 1);
    int tid = threadIdx.x;
    int m = tid >> 3, ns = tid & 7;
    size_t base = (size_t)bh * L_ * N_;

    float S[8], w[8], uk[8];
    #pragma unroll
    for (int i = 0; i < 8; i++) {
        int n = ns * 8 + i;
        w[i] = expf(-expf(td[h * N_ + n]));
        uk[i] = tf[h * N_ + n];
        S[i] = 0.f;
    }

    uint32_t sr = smem_u32(rs), sk = smem_u32(ks), sv = smem_u32(vs);
    const int NCH = L_ / SCH;
    uint32_t toff = (uint32_t)tid * 16;

    cp16(sr + toff, rr + base + tid * 4);
    cp16(sk + toff, kk + base + tid * 4);
    cp16(sv + toff, vv + base + tid * 4);
    asm volatile("cp.async.commit_group;");
    asm volatile("cp.async.wait_group 0;");
    __syncthreads();

    int gm = mh * 32 + m;
    for (int ch = 0; ch < NCH; ch++) {
        int q = ch & 1;
        if (ch + 1 < NCH) {
            uint32_t dst = (uint32_t)((q ^ 1) * SCH * 64 * 4) + toff;
            size_t gof = base + (size_t)(ch + 1) * SCH * 64 + tid * 4;
            cp16(sr + dst, rr + gof);
            cp16(sk + dst, kk + gof);
            cp16(sv + dst, vv + gof);
            asm volatile("cp.async.commit_group;");
        }
        const float* rb = rs[q];
        const float* kb = ks[q];
        const float* vb = vs[q];
        size_t yof = base + (size_t)ch * SCH * 64 + gm;
        #pragma unroll 4
        for (int s = 0; s < SCH; s++) {
            const float* rp = rb + s * 64 + ns * 8;
            const float* kp = kb + s * 64 + ns * 8;
            float vm = vb[s * 64 + gm];
            float t = 0.f, qq = 0.f;
            #pragma unroll
            for (int i = 0; i < 8; i += 4) {
                float4 r4 = *(const float4*)(rp + i);
                float4 k4 = *(const float4*)(kp + i);
                float rv[4] = {r4.x, r4.y, r4.z, r4.w};
                float kv[4] = {k4.x, k4.y, k4.z, k4.w};
                #pragma unroll
                for (int j = 0; j < 4; j++) {
                    int i2 = i + j;
                    t += rv[j] * S[i2];
                    qq += rv[j] * uk[i2] * kv[j];
                    S[i2] = w[i2] * S[i2] + kv[j] * vm;
                }
            }
            t  += __shfl_xor_sync(0xffffffffu, t, 1);
            t  += __shfl_xor_sync(0xffffffffu, t, 2);
            t  += __shfl_xor_sync(0xffffffffu, t, 4);
            qq += __shfl_xor_sync(0xffffffffu, qq, 1);
            qq += __shfl_xor_sync(0xffffffffu, qq, 2);
            qq += __shfl_xor_sync(0xffffffffu, qq, 4);
            if (ns == 0) yy[yof + (size_t)s * 64] = t + qq * vm;
        }
        if (ch + 1 < NCH) asm volatile("cp.async.wait_group 0;");
        __syncthreads();
    }
}

// ---------------- groupnorm * ln_x * gate -> fp16 (B,L,C) ----------------
__global__ void __launch_bounds__(256)
gnorm_k(const float* __restrict__ yy, const float* __restrict__ gate,
        const float* __restrict__ lnw, const float* __restrict__ lnb,
        __half* __restrict__ z) {
    int b = blockIdx.z, h = blockIdx.y, l0 = blockIdx.x * 64;
    __shared__ float tile[64][65];
    __shared__ float rs1[4][64], rs2[4][64];
    __shared__ float smean[64], sinv[64];
    int tid = threadIdx.x;
    size_t ybase = ((size_t)(b * H_ + h) * L_ + l0) * N_;

    #pragma unroll
    for (int i = 0; i < 16; i++) {
        int id = tid + i * 256;
        int row = id >> 6, col = id & 63;
        tile[col][row] = yy[ybase + (size_t)row * N_ + col];
    }
    __syncthreads();
    {
        int l = tid & 63, part = tid >> 6;
        float s1 = 0.f, s2 = 0.f;
        #pragma unroll
        for (int i = 0; i < 16; i++) {
            float v = tile[part * 16 + i][l];
            s1 += v; s2 += v * v;
        }
        rs1[part][l] = s1; rs2[part][l] = s2;
    }
    __syncthreads();
    if (tid < 64) {
        float s1 = rs1[0][tid] + rs1[1][tid] + rs1[2][tid] + rs1[3][tid];
        float s2 = rs2[0][tid] + rs2[1][tid] + rs2[2][tid] + rs2[3][tid];
        float mean = s1 * (1.f / 64);
        float var = s2 * (1.f / 64) - mean * mean;
        smean[tid] = mean;
        sinv[tid] = rsqrtf(var + 1e-5f);
    }
    __syncthreads();

    int n = tid >> 2, lq = tid & 3;
    int c = h * 64 + n;
    float lw = lnw[c], lb = lnb[c];
    #pragma unroll
    for (int q = 0; q < 16; q++) {
        int l = lq * 16 + q;
        size_t rofs = ((size_t)b * L_ + l0 + l) * C_ + c;
        float v = ((tile[n][l] - smean[l]) * sinv[l] * lw + lb) * gate[rofs];
        z[rofs] = __float2half(v);
    }
}

// ---------------- residual + rms ----------------
__global__ void __launch_bounds__(128)
resid_rms_k(const float* __restrict__ img, const float* __restrict__ txt,
            const float* __restrict__ attn, const float* __restrict__ mod,
            const float* __restrict__ w2i, const float* __restrict__ w2t,
            float* __restrict__ img1, float* __restrict__ txt1,
            float* __restrict__ himg, float* __restrict__ htxt) {
    int b = blockIdx.y;
    int l = blockIdx.x * 128 + threadIdx.x;
    int s, li, Ls;
    const float* src; float* d1; float* dh; const float* rw;
    if (l < LI_) { s = 0; li = l;       Ls = LI_; src = img; d1 = img1; dh = himg; rw = w2i; }
    else         { s = 1; li = l - LI_; Ls = LT_; src = txt; d1 = txt1; dh = htxt; rw = w2t; }
    const float* mb = mod + (s * B_ + b) * 6 * C_;
    const float* ap = attn + (size_t)b * C_ * L_ + l;
    const float* sp = src + (size_t)b * C_ * Ls + li;
    float* p1 = d1 + (size_t)b * C_ * Ls + li;
    float* ph = dh + (size_t)b * C_ * Ls + li;
    float ss = 0.f;
    #pragma unroll 4
    for (int c = 0; c < C_; c++) {
        float v = sp[(size_t)c * Ls] + mb[2 * C_ + c] * ap[(size_t)c * L_];
        p1[(size_t)c * Ls] = v;
        ss += v * v;
    }
    float inv = rsqrtf(ss * (1.f / C_) + 1e-6f);
    #pragma unroll 4
    for (int c = 0; c < C_; c++) {
        float v = p1[(size_t)c * Ls];
        ph[(size_t)c * Ls] = v * inv * rw[c] * (1.f + mb[4 * C_ + c]) + mb[3 * C_ + c];
    }
}

// ---------------- host ----------------
static float* symaddr(const void* s) {
    void* p = nullptr;
    cudaGetSymbolAddress(&p, s);
    return (float*)p;
}
static __half* symaddrh(const void* s) {
    void* p = nullptr;
    cudaGetSymbolAddress(&p, s);
    return (__half*)p;
}

extern "C" void kernel_launch(void* const* d_in, const int* in_sizes, int n_in,
                              void* d_out, int out_size) {
    const float* img   = (const float*)d_in[0];
    const float* txt   = (const float*)d_in[1];
    const float* cond  = (const float*)d_in[2];
    const float* Wmi   = (const float*)d_in[3];
    const float* bmi   = (const float*)d_in[4];
    const float* Wmt   = (const float*)d_in[5];
    const float* bmt   = (const float*)d_in[6];
    const float* rmsi  = (const float*)d_in[7];
    const float* rmst  = (const float*)d_in[8];
    const float* rmsi2 = (const float*)d_in[9];
    const float* rmst2 = (const float*)d_in[10];
    const float* mur   = (const float*)d_in[11];
    const float* muk   = (const float*)d_in[12];
    const float* muv   = (const float*)d_in[13];
    const float* mug   = (const float*)d_in[14];
    const float* Wr    = (const float*)d_in[15];
    const float* Wk    = (const float*)d_in[16];
    const float* Wv    = (const float*)d_in[17];
    const float* Wg    = (const float*)d_in[18];
    const float* Wo    = (const float*)d_in[19];
    const float* td    = (const float*)d_in[20];
    const float* tf    = (const float*)d_in[21];
    const float* lnw   = (const float*)d_in[22];
    const float* lnb   = (const float*)d_in[23];
    const float* fi1   = (const float*)d_in[24];
    const float* fi2   = (const float*)d_in[25];
    const float* ft1   = (const float*)d_in[26];
    const float* ft2   = (const float*)d_in[27];

    float* p_mod   = symaddr(g_mod);
    float* p_inv   = symaddr(g_inv);
    float* p_gate  = symaddr(g_gate);
    float* p_r     = symaddr(g_r);
    float* p_k     = symaddr(g_k);
    float* p_v     = symaddr(g_v);
    float* p_y     = symaddr(g_y);
    float* p_attn  = symaddr(g_attn);
    float* p_img1  = symaddr(g_img1);
    float* p_txt1  = symaddr(g_txt1);
    float* p_himg  = symaddr(g_himg);
    float* p_htxt  = symaddr(g_htxt);

    __half* pArkvg = symaddrh(g_Arkvg);
    __half* pAwo   = symaddrh(g_Awo);
    __half* pAfi1  = symaddrh(g_Afi1);
    __half* pAfi2  = symaddrh(g_Afi2);
    __half* pAft1  = symaddrh(g_Aft1);
    __half* pAft2  = symaddrh(g_Aft2);
    __half* pBx4   = symaddrh(g_Bx4);
    __half* pBz    = symaddrh(g_Bz);
    __half* pBhi   = symaddrh(g_Bhi);
    __half* pBht   = symaddrh(g_Bht);
    __half* pBmi   = symaddrh(g_Bmi);
    __half* pBmt   = symaddrh(g_Bmt);

    float* out_img = (float*)d_out;
    float* out_txt = out_img + IMGSZ;

    cudaFuncSetAttribute(gemm_mma<0>, cudaFuncAttributeMaxDynamicSharedMemorySize, GSMEM);
    cudaFuncSetAttribute(gemm_mma<1>, cudaFuncAttributeMaxDynamicSharedMemorySize, GSMEM);
    cudaFuncSetAttribute(gemm_mma<2>, cudaFuncAttributeMaxDynamicSharedMemorySize, GSMEM);
    cudaFuncSetAttribute(gemm_mma<3>, cudaFuncAttributeMaxDynamicSharedMemorySize, GSMEM);

    // 0) fused modulation + rms sums
    prep_k<<<MOD_BLOCKS + RMS_BLOCKS, 256>>>(cond, Wmi, bmi, Wmt, bmt, img, txt,
                                             p_mod, p_inv);
    // 1) rkvg weight pack
    wpack4_k<<<(4 * 1024 * 1024) / 256, 256>>>(Wr, Wk, Wv, Wg, pArkvg);
    // 2) mixed inputs (B,L,C) x4 parts
    bxmix_k<<<dim3(L_ / 32, C_ / 32, B_), 256>>>(img, txt, rmsi, rmst, p_mod, p_inv,
                                                 mur, muk, muv, mug, pBx4);
    // 3) fused rkvg GEMM  (profiled launch)
    gemm_mma<1><<<dim3(L_ / 128, 4096 / 128, B_), 256, GSMEM>>>(
        pArkvg, pBx4, nullptr, nullptr, p_r, p_k, p_v, p_gate,
        nullptr, nullptr, 4096, 1024, L_);

    // remaining weight packs
    wsplit1_plain_k<<<(1024 * 1024) / 256, 256>>>(Wo,  pAwo,  (size_t)1024 * 1024);
    wsplit1_plain_k<<<(2048 * 1024) / 256, 256>>>(fi1, pAfi1, (size_t)2048 * 1024);
    wsplit1_plain_k<<<(1024 * 2048) / 256, 256>>>(fi2, pAfi2, (size_t)1024 * 2048);
    wsplit1_plain_k<<<(2048 * 1024) / 256, 256>>>(ft1, pAft1, (size_t)2048 * 1024);
    wsplit1_plain_k<<<(1024 * 2048) / 256, 256>>>(ft2, pAft2, (size_t)1024 * 2048);

    // scan (64 blocks: (b,h) x m-half)
    scan_k<<<B_ * H_ * 2, 256>>>(p_r, p_k, p_v, td, tf, p_y);

    // groupnorm * gate -> fp16 (B,L,C)
    gnorm_k<<<dim3(L_ / 64, H_, B_), 256>>>(p_y, p_gate, lnw, lnb, pBz);

    // Wo GEMM -> attn (B,C,L)
    gemm_mma<0><<<dim3(L_ / 128, C_ / 128, B_), 256, GSMEM>>>(
        pAwo, pBz, p_attn, nullptr, nullptr, nullptr, nullptr, nullptr,
        nullptr, nullptr, C_, 1024, L_);

    // residual + rms
    resid_rms_k<<<dim3(L_ / 128, B_), 128>>>(img, txt, p_attn, p_mod, rmsi2, rmst2,
                                             p_img1, p_txt1, p_himg, p_htxt);

    // FFN img
    asplit1_k<<<dim3(LI_ / 32, C_ / 32, B_), 256>>>(p_himg, pBhi, C_, LI_);
    gemm_mma<2><<<dim3(LI_ / 128, HID_ / 128, B_), 256, GSMEM>>>(
        pAfi1, pBhi, nullptr, pBmi, nullptr, nullptr, nullptr, nullptr,
        nullptr, nullptr, HID_, 1024, LI_);
    gemm_mma<3><<<dim3(LI_ / 128, C_ / 128, B_), 256, GSMEM>>>(
        pAfi2, pBmi, out_img, nullptr, nullptr, nullptr, nullptr, nullptr,
        p_img1, p_mod + 5 * C_, C_, 2048, LI_);

    // FFN txt
    asplit1_k<<<dim3(LT_ / 32, C_ / 32, B_), 256>>>(p_htxt, pBht, C_, LT_);
    gemm_mma<2><<<dim3(LT_ / 128, HID_ / 128, B_), 256, GSMEM>>>(
        pAft1, pBht, nullptr, pBmt, nullptr, nullptr, nullptr, nullptr,
        nullptr, nullptr, HID_, 1024, LT_);
    gemm_mma<3><<<dim3(LT_ / 128, C_ / 128, B_), 256, GSMEM>>>(
        pAft2, pBmt, out_txt, nullptr, nullptr, nullptr, nullptr, nullptr,
        p_txt1, p_mod + B_ * 6 * C_ + 5 * C_, C_, 2048, LT_);
}